// round 4
// baseline (speedup 1.0000x reference)
#include <cuda_runtime.h>
#include <math.h>

// ---------------- problem constants ----------------
#define B    16
#define T1   800
#define T2   200
#define CATT 80

typedef unsigned long long u64;

__device__ __forceinline__ u64 pk2(float lo, float hi) {
    u64 r; asm("mov.b64 %0,{%1,%2};" : "=l"(r) : "f"(lo), "f"(hi)); return r;
}
__device__ __forceinline__ void upk2(u64 v, float& lo, float& hi) {
    asm("mov.b64 {%0,%1},%2;" : "=f"(lo), "=f"(hi) : "l"(v));
}
__device__ __forceinline__ void ffma2(u64& d, u64 a, u64 b) {
    asm("fma.rn.f32x2 %0,%1,%2,%0;" : "+l"(d) : "l"(a), "l"(b));
}

// ---------------- scratch ----------------
__device__ float g_k1[B * 512 * T2];   // key conv1 out
__device__ float g_k [B * CATT * T2];  // key encoder out
__device__ float g_q1[B * 160 * T1];   // query conv1 out
__device__ float g_q [B * CATT * T1];  // query encoder out

// ============================================================
// k=3 conv body, pad=1, f32x2, double-buffered, CK=8.
// 128 threads, micro 4co x 8t:  (TCO/4)*(TT/8) == 128.
// ============================================================
template<int TCO, int TT, int CIN, int RELU>
__device__ __forceinline__ void conv3_body(
    const float* __restrict__ xb,   // x + b*CIN*T
    const float* __restrict__ w,    // (COUT, CIN, 3)
    const float* __restrict__ bias,
    float* __restrict__ yb,         // y + b*COUT*T
    int T, int co0, int t0, int tid, char* smraw)
{
    constexpr int CK   = 8;
    constexpr int XROW = TT + 4;
    constexpr int WROW = CK * 3 + 1;   // 25 float2, pad breaks conflicts
    constexpr int NC   = CIN / CK;
    constexpr int TTHR = TT / 8;
    constexpr int XTOT = CK * (TT + 2);
    constexpr int WTOT = TCO * CK * 3;         // scalars per chunk
    constexpr int XLD  = (XTOT + 127) / 128;
    constexpr int WLD  = WTOT / 128;
    static_assert((TCO / 4) * TTHR == 128, "layout");
    static_assert(WTOT % 128 == 0, "wld");

    float*  Xs = (float*)smraw;                                   // 2*CK*XROW
    float2* Ws = (float2*)(smraw + 2 * CK * XROW * sizeof(float));// 2*TCO*WROW

    const int ci = tid / TTHR;   // 0..TCO/4-1
    const int tj = tid % TTHR;

    u64 acc[4][4];
    #pragma unroll
    for (int i = 0; i < 4; i++)
        #pragma unroll
        for (int p = 0; p < 4; p++) acc[i][p] = 0ull;

    float xr_[XLD], wr_[WLD];

    // prefetch chunk 0
    #pragma unroll
    for (int i = 0; i < XLD; i++) {
        int e = tid + i * 128;
        if (e < XTOT) {
            int r = e / (TT + 2), cc = e % (TT + 2);
            int t = t0 + cc - 1;
            xr_[i] = (t >= 0 && t < T) ? xb[(size_t)r * T + t] : 0.f;
        }
    }
    #pragma unroll
    for (int i = 0; i < WLD; i++) {
        int e = tid + i * 128;
        int r = e / (CK * 3), cc = e % (CK * 3);
        wr_[i] = w[(size_t)(co0 + r) * (CIN * 3) + cc];
    }
    #pragma unroll
    for (int i = 0; i < XLD; i++) {
        int e = tid + i * 128;
        if (e < XTOT) { int r = e / (TT + 2), cc = e % (TT + 2); Xs[r * XROW + cc] = xr_[i]; }
    }
    #pragma unroll
    for (int i = 0; i < WLD; i++) {
        int e = tid + i * 128;
        int r = e / (CK * 3), cc = e % (CK * 3);
        Ws[r * WROW + cc] = make_float2(wr_[i], wr_[i]);
    }
    __syncthreads();

    for (int c = 0; c < NC; c++) {
        if (c + 1 < NC) {
            const int c0 = (c + 1) * CK;
            #pragma unroll
            for (int i = 0; i < XLD; i++) {
                int e = tid + i * 128;
                if (e < XTOT) {
                    int r = e / (TT + 2), cc = e % (TT + 2);
                    int t = t0 + cc - 1;
                    xr_[i] = (t >= 0 && t < T) ? xb[(size_t)(c0 + r) * T + t] : 0.f;
                }
            }
            #pragma unroll
            for (int i = 0; i < WLD; i++) {
                int e = tid + i * 128;
                int r = e / (CK * 3), cc = e % (CK * 3);
                wr_[i] = w[(size_t)(co0 + r) * (CIN * 3) + (size_t)c0 * 3 + cc];
            }
        }
        const float*  X = Xs + (c & 1) * CK * XROW;
        const float2* W = Ws + (c & 1) * TCO * WROW;
        #pragma unroll
        for (int ck = 0; ck < CK; ck++) {
            const float* xp = X + ck * XROW + tj * 8;
            float4 xa = *(const float4*)xp;
            float4 xb4 = *(const float4*)(xp + 4);
            float x8 = xp[8], x9 = xp[9];
            u64 e0 = pk2(xa.x, xa.y), e1 = pk2(xa.z, xa.w);
            u64 e2 = pk2(xb4.x, xb4.y), e3 = pk2(xb4.z, xb4.w);
            u64 e4 = pk2(x8, x9);
            u64 o0 = pk2(xa.y, xa.z), o1 = pk2(xa.w, xb4.x);
            u64 o2 = pk2(xb4.y, xb4.z), o3 = pk2(xb4.w, x8);
            #pragma unroll
            for (int i = 0; i < 4; i++) {
                const u64* wp = (const u64*)(W + (size_t)(ci * 4 + i) * WROW + ck * 3);
                u64 w0 = wp[0], w1 = wp[1], w2 = wp[2];
                ffma2(acc[i][0], e0, w0); ffma2(acc[i][1], e1, w0);
                ffma2(acc[i][2], e2, w0); ffma2(acc[i][3], e3, w0);
                ffma2(acc[i][0], o0, w1); ffma2(acc[i][1], o1, w1);
                ffma2(acc[i][2], o2, w1); ffma2(acc[i][3], o3, w1);
                ffma2(acc[i][0], e1, w2); ffma2(acc[i][1], e2, w2);
                ffma2(acc[i][2], e3, w2); ffma2(acc[i][3], e4, w2);
            }
        }
        if (c + 1 < NC) {
            __syncthreads();
            float*  Xd = Xs + ((c + 1) & 1) * CK * XROW;
            float2* Wd = Ws + ((c + 1) & 1) * TCO * WROW;
            #pragma unroll
            for (int i = 0; i < XLD; i++) {
                int e = tid + i * 128;
                if (e < XTOT) { int r = e / (TT + 2), cc = e % (TT + 2); Xd[r * XROW + cc] = xr_[i]; }
            }
            #pragma unroll
            for (int i = 0; i < WLD; i++) {
                int e = tid + i * 128;
                int r = e / (CK * 3), cc = e % (CK * 3);
                Wd[r * WROW + cc] = make_float2(wr_[i], wr_[i]);
            }
            __syncthreads();
        }
    }

    #pragma unroll
    for (int i = 0; i < 4; i++) {
        int co = co0 + ci * 4 + i;
        float bb = bias[co];
        float v[8];
        #pragma unroll
        for (int p = 0; p < 4; p++) upk2(acc[i][p], v[2 * p], v[2 * p + 1]);
        #pragma unroll
        for (int j = 0; j < 8; j++) {
            int t = t0 + tj * 8 + j;
            if (t < T) {
                float o = v[j] + bb;
                if (RELU) o = fmaxf(o, 0.f);
                yb[(size_t)co * T + t] = o;
            }
        }
    }
}

// ---- kernel A: key conv1 (256->512 k3) + query conv1 (80->160 k3) ----
#define KEY_A_BLKS (4 * 7 * B)     // 448: 4 co-tiles(128) x 7 t-tiles(32)
#define QRY_A_BLKS (5 * 7 * B)     // 560: 5 co-tiles(32)  x 7 t-tiles(128)
__global__ __launch_bounds__(128) void convA(
    const float* __restrict__ keys, const float* __restrict__ kw1,
    const float* __restrict__ kb1, float* __restrict__ k1out,
    const float* __restrict__ qsrc, const float* __restrict__ qw1,
    const float* __restrict__ qb1, float* __restrict__ q1out)
{
    extern __shared__ char sm[];
    const int bid = blockIdx.x, tid = threadIdx.x;
    if (bid < KEY_A_BLKS) {
        int b = bid / 28, r = bid % 28;
        int co0 = (r / 7) * 128, t0 = (r % 7) * 32;
        conv3_body<128, 32, 256, 1>(keys + (size_t)b * 256 * T2, kw1, kb1,
                                    k1out + (size_t)b * 512 * T2, T2, co0, t0, tid, sm);
    } else {
        int qb = bid - KEY_A_BLKS;
        int b = qb / 35, r = qb % 35;
        int co0 = (r / 7) * 32, t0 = (r % 7) * 128;
        conv3_body<32, 128, 80, 1>(qsrc + (size_t)b * 80 * T1, qw1, qb1,
                                   q1out + (size_t)b * 160 * T1, T1, co0, t0, tid, sm);
    }
}

// ============================================================
// k=1 accumulate body: 80 couts x 64 t tile, micro 5co x 8t, CK=16.
// 128 threads: ci=tid/8 (16 -> 5co each), tj=tid%8 (8t each).
// ============================================================
template<int CIN>
__device__ __forceinline__ void k1_accum(
    const float* __restrict__ xb, int T, int t0,
    const float* __restrict__ w,   // (80, CIN)
    float* Xs, float2* Ws, u64 (&acc)[5][4], int tid)
{
    constexpr int CK = 16, XROW = 68, WROW = 17;
    constexpr int NC = CIN / CK;
    constexpr int WLD = 80 * CK / 128;   // 10
    constexpr int XLD = CK * 64 / 128;   // 8
    const int ci = tid >> 3, tj = tid & 7;

    float wr_[WLD], xr_[XLD];
    #pragma unroll
    for (int i = 0; i < WLD; i++) {
        int e = tid + i * 128; int r = e / CK, cc = e % CK;
        wr_[i] = w[(size_t)r * CIN + cc];
    }
    #pragma unroll
    for (int i = 0; i < XLD; i++) {
        int e = tid + i * 128; int r = e / 64, cc = e % 64;
        int t = t0 + cc;
        xr_[i] = (t < T) ? xb[(size_t)r * T + t] : 0.f;
    }
    #pragma unroll
    for (int i = 0; i < WLD; i++) {
        int e = tid + i * 128; int r = e / CK, cc = e % CK;
        Ws[r * WROW + cc] = make_float2(wr_[i], wr_[i]);
    }
    #pragma unroll
    for (int i = 0; i < XLD; i++) {
        int e = tid + i * 128; int r = e / 64, cc = e % 64;
        Xs[r * XROW + cc] = xr_[i];
    }
    __syncthreads();

    for (int c = 0; c < NC; c++) {
        if (c + 1 < NC) {
            const int c0 = (c + 1) * CK;
            #pragma unroll
            for (int i = 0; i < WLD; i++) {
                int e = tid + i * 128; int r = e / CK, cc = e % CK;
                wr_[i] = w[(size_t)r * CIN + c0 + cc];
            }
            #pragma unroll
            for (int i = 0; i < XLD; i++) {
                int e = tid + i * 128; int r = e / 64, cc = e % 64;
                int t = t0 + cc;
                xr_[i] = (t < T) ? xb[(size_t)(c0 + r) * T + t] : 0.f;
            }
        }
        const float*  X = Xs + (c & 1) * CK * XROW;
        const float2* W = Ws + (c & 1) * 80 * WROW;
        #pragma unroll
        for (int ck = 0; ck < CK; ck++) {
            const float* xp = X + ck * XROW + tj * 8;
            float4 xa = *(const float4*)xp;
            float4 xc = *(const float4*)(xp + 4);
            u64 e0 = pk2(xa.x, xa.y), e1 = pk2(xa.z, xa.w);
            u64 e2 = pk2(xc.x, xc.y), e3 = pk2(xc.z, xc.w);
            #pragma unroll
            for (int i = 0; i < 5; i++) {
                u64 wv = *(const u64*)(W + (size_t)(ci * 5 + i) * WROW + ck);
                ffma2(acc[i][0], e0, wv); ffma2(acc[i][1], e1, wv);
                ffma2(acc[i][2], e2, wv); ffma2(acc[i][3], e3, wv);
            }
        }
        if (c + 1 < NC) {
            __syncthreads();
            float*  Xd = Xs + ((c + 1) & 1) * CK * XROW;
            float2* Wd = Ws + ((c + 1) & 1) * 80 * WROW;
            #pragma unroll
            for (int i = 0; i < WLD; i++) {
                int e = tid + i * 128; int r = e / CK, cc = e % CK;
                Wd[r * WROW + cc] = make_float2(wr_[i], wr_[i]);
            }
            #pragma unroll
            for (int i = 0; i < XLD; i++) {
                int e = tid + i * 128; int r = e / 64, cc = e % 64;
                Xd[r * XROW + cc] = xr_[i];
            }
            __syncthreads();
        }
    }
}

// ---- kernel B: key conv2 (512->80 k1) + fused query conv2+3 ----
#define KEY_B_BLKS (4 * B)     // 64: 4 t-tiles(64)
#define QRY_B_BLKS (13 * B)    // 208: 13 t-tiles(64)
#define HROW 68
__global__ __launch_bounds__(128) void convB(
    const float* __restrict__ k1in, const float* __restrict__ kw2,
    const float* __restrict__ kb2, float* __restrict__ kout,
    const float* __restrict__ q1in,
    const float* __restrict__ qw2, const float* __restrict__ qb2,
    const float* __restrict__ qw3, const float* __restrict__ qb3,
    float* __restrict__ qout)
{
    extern __shared__ char sm[];
    float*  Xs  = (float*)sm;                              // 2*16*68
    float2* Ws  = (float2*)(sm + 2 * 16 * 68 * 4);         // 2*80*17
    float*  Hs  = (float*)((char*)Ws + 2 * 80 * 17 * 8);   // 80*68
    float*  W3s = Hs + 80 * HROW;                          // 80*80

    const int bid = blockIdx.x, tid = threadIdx.x;
    const int ci = tid >> 3, tj = tid & 7;

    u64 acc[5][4];
    #pragma unroll
    for (int i = 0; i < 5; i++)
        #pragma unroll
        for (int p = 0; p < 4; p++) acc[i][p] = 0ull;

    if (bid < KEY_B_BLKS) {
        int b = bid / 4, t0 = (bid % 4) * 64;
        k1_accum<512>(k1in + (size_t)b * 512 * T2, T2, t0, kw2, Xs, Ws, acc, tid);
        float* yb = kout + (size_t)b * 80 * T2;
        #pragma unroll
        for (int i = 0; i < 5; i++) {
            int co = ci * 5 + i;
            float bb = kb2[co];
            float v[8];
            #pragma unroll
            for (int p = 0; p < 4; p++) upk2(acc[i][p], v[2 * p], v[2 * p + 1]);
            #pragma unroll
            for (int j = 0; j < 8; j++) {
                int t = t0 + tj * 8 + j;
                if (t < T2) yb[(size_t)co * T2 + t] = v[j] + bb;
            }
        }
    } else {
        int qb = bid - KEY_B_BLKS;
        int b = qb / 13, t0 = (qb % 13) * 64;
        // preload W3 (plain floats)
        for (int e = tid; e < 6400; e += 128) W3s[e] = qw3[e];
        k1_accum<160>(q1in + (size_t)b * 160 * T1, T1, t0, qw2, Xs, Ws, acc, tid);
        // h = relu(acc + b2) -> Hs
        #pragma unroll
        for (int i = 0; i < 5; i++) {
            int co = ci * 5 + i;
            float bb = qb2[co];
            float v[8];
            #pragma unroll
            for (int p = 0; p < 4; p++) upk2(acc[i][p], v[2 * p], v[2 * p + 1]);
            float4 h0, h1;
            h0.x = fmaxf(v[0] + bb, 0.f); h0.y = fmaxf(v[1] + bb, 0.f);
            h0.z = fmaxf(v[2] + bb, 0.f); h0.w = fmaxf(v[3] + bb, 0.f);
            h1.x = fmaxf(v[4] + bb, 0.f); h1.y = fmaxf(v[5] + bb, 0.f);
            h1.z = fmaxf(v[6] + bb, 0.f); h1.w = fmaxf(v[7] + bb, 0.f);
            *(float4*)(Hs + (size_t)co * HROW + tj * 8) = h0;
            *(float4*)(Hs + (size_t)co * HROW + tj * 8 + 4) = h1;
        }
        __syncthreads();

        u64 acc2[5][4];
        #pragma unroll
        for (int i = 0; i < 5; i++)
            #pragma unroll
            for (int p = 0; p < 4; p++) acc2[i][p] = 0ull;

        #pragma unroll 4
        for (int ck = 0; ck < 80; ck++) {
            const float* xp = Hs + (size_t)ck * HROW + tj * 8;
            float4 xa = *(const float4*)xp;
            float4 xc = *(const float4*)(xp + 4);
            u64 e0 = pk2(xa.x, xa.y), e1 = pk2(xa.z, xa.w);
            u64 e2 = pk2(xc.x, xc.y), e3 = pk2(xc.z, xc.w);
            #pragma unroll
            for (int i = 0; i < 5; i++) {
                float wv = W3s[(size_t)(ci * 5 + i) * 80 + ck];
                u64 wp = pk2(wv, wv);
                ffma2(acc2[i][0], e0, wp); ffma2(acc2[i][1], e1, wp);
                ffma2(acc2[i][2], e2, wp); ffma2(acc2[i][3], e3, wp);
            }
        }

        float* yb = qout + (size_t)b * 80 * T1;
        #pragma unroll
        for (int i = 0; i < 5; i++) {
            int co = ci * 5 + i;
            float bb = qb3[co];
            float v[8];
            #pragma unroll
            for (int p = 0; p < 4; p++) upk2(acc2[i][p], v[2 * p], v[2 * p + 1]);
            #pragma unroll
            for (int j = 0; j < 8; j++) {
                int t = t0 + tj * 8 + j;
                if (t < T1) yb[(size_t)co * T1 + t] = v[j] + bb;
            }
        }
    }
}

// ============================================================
// Attention: dist -> log_softmax over T2 -> + log(prior+1e-8)
// ============================================================
#define KROW 224
__global__ __launch_bounds__(256) void attn_kernel(
    const float* __restrict__ q, const float* __restrict__ k,
    const float* __restrict__ prior, float* __restrict__ out)
{
    extern __shared__ float smf[];
    float* ks  = smf;                // 80 * 224
    float* qs  = ks + 80 * KROW;     // 80 * 32
    float* k2s = qs + 80 * 32;       // 224
    float* q2s = k2s + KROW;         // 32

    const int b   = blockIdx.y;
    const int t10 = blockIdx.x * 32;
    const int tid = threadIdx.x;

    const float* kb = k + (size_t)b * CATT * T2;
    const float* qb = q + (size_t)b * CATT * T1;

    for (int idx = tid; idx < 80 * KROW; idx += 256) {
        int c = idx / KROW, t = idx % KROW;
        ks[idx] = (t < T2) ? kb[(size_t)c * T2 + t] : 0.f;
    }
    for (int idx = tid; idx < 80 * 32; idx += 256) {
        int c = idx / 32, i = idx % 32;
        qs[idx] = qb[(size_t)c * T1 + t10 + i];
    }
    __syncthreads();

    if (tid < KROW) {
        float s = 0.f;
        #pragma unroll 8
        for (int c = 0; c < 80; c++) { float v = ks[c * KROW + tid]; s += v * v; }
        k2s[tid] = s;
    } else {
        int i = tid - KROW;
        if (i < 32) {
            float s = 0.f;
            #pragma unroll 8
            for (int c = 0; c < 80; c++) { float v = qs[c * 32 + i]; s += v * v; }
            q2s[i] = s;
        }
    }
    __syncthreads();

    const int warp = tid / 32;
    const int lane = tid % 32;

    u64 dp[2][7];
    #pragma unroll
    for (int p = 0; p < 2; p++)
        #pragma unroll
        for (int j = 0; j < 7; j++) dp[p][j] = 0ull;

    #pragma unroll 4
    for (int c = 0; c < 80; c++) {
        float4 q4 = *(const float4*)&qs[c * 32 + warp * 4];
        u64 qp0 = pk2(q4.x, q4.y), qp1 = pk2(q4.z, q4.w);
        #pragma unroll
        for (int j = 0; j < 7; j++) {
            float kv = ks[c * KROW + lane + 32 * j];
            u64 kp = pk2(kv, kv);
            ffma2(dp[0][j], qp0, kp);
            ffma2(dp[1][j], qp1, kp);
        }
    }

    float dot[4][7];
    #pragma unroll
    for (int p = 0; p < 2; p++)
        #pragma unroll
        for (int j = 0; j < 7; j++) upk2(dp[p][j], dot[2 * p][j], dot[2 * p + 1][j]);

    const bool last_valid = (lane + 192) < T2;

    #pragma unroll
    for (int i = 0; i < 4; i++) {
        int r  = warp * 4 + i;
        int t1 = t10 + r;
        float q2 = q2s[r];
        float xv[7];
        #pragma unroll
        for (int j = 0; j < 7; j++) {
            int t2 = lane + 32 * j;
            bool valid = (j < 6) || last_valid;
            xv[j] = valid ? (-0.0005f * (q2 + k2s[t2] - 2.f * dot[i][j])) : -1e30f;
        }
        float m = xv[0];
        #pragma unroll
        for (int j = 1; j < 7; j++) m = fmaxf(m, xv[j]);
        #pragma unroll
        for (int off = 16; off; off >>= 1)
            m = fmaxf(m, __shfl_xor_sync(0xFFFFFFFFu, m, off));
        float s = 0.f;
        #pragma unroll
        for (int j = 0; j < 7; j++) {
            bool valid = (j < 6) || last_valid;
            if (valid) s += __expf(xv[j] - m);
        }
        #pragma unroll
        for (int off = 16; off; off >>= 1)
            s += __shfl_xor_sync(0xFFFFFFFFu, s, off);
        float lse = m + __logf(s);

        const float* pr = prior + ((size_t)b * T1 + t1) * T2;
        float* ob = out + ((size_t)b * T1 + t1) * T2;
        #pragma unroll
        for (int j = 0; j < 7; j++) {
            int t2 = lane + 32 * j;
            bool valid = (j < 6) || last_valid;
            if (valid)
                ob[t2] = xv[j] - lse + __logf(pr[t2] + 1e-8f);
        }
    }
}

// ============================================================
// launch
// ============================================================
extern "C" void kernel_launch(void* const* d_in, const int* in_sizes, int n_in,
                              void* d_out, int out_size)
{
    const float* queries = (const float*)d_in[0];
    const float* keys    = (const float*)d_in[1];
    const float* prior   = (const float*)d_in[2];
    const float* kw1 = (const float*)d_in[3];
    const float* kb1 = (const float*)d_in[4];
    const float* kw2 = (const float*)d_in[5];
    const float* kb2 = (const float*)d_in[6];
    const float* qw1 = (const float*)d_in[7];
    const float* qb1 = (const float*)d_in[8];
    const float* qw2 = (const float*)d_in[9];
    const float* qb2 = (const float*)d_in[10];
    const float* qw3 = (const float*)d_in[11];
    const float* qb3 = (const float*)d_in[12];
    float* out = (float*)d_out;

    float *p_k1, *p_k, *p_q1, *p_q;
    cudaGetSymbolAddress((void**)&p_k1, g_k1);
    cudaGetSymbolAddress((void**)&p_k,  g_k);
    cudaGetSymbolAddress((void**)&p_q1, g_q1);
    cudaGetSymbolAddress((void**)&p_q,  g_q);

    // smem sizes
    // A: max(key: 2*8*36*4 + 2*128*25*8, query: 2*8*132*4 + 2*32*25*8)
    const int SM_A = 2 * 8 * 36 * 4 + 2 * 128 * 25 * 8;             // 53504
    // B: Xs 2*16*68*4 + Ws 2*80*17*8 + Hs 80*68*4 + W3 80*80*4
    const int SM_B = 2 * 16 * 68 * 4 + 2 * 80 * 17 * 8 + 80 * HROW * 4 + 6400 * 4; // 77824
    const int SM_C = (80 * KROW + 80 * 32 + KROW + 32) * 4;         // 82944

    cudaFuncSetAttribute(convA, cudaFuncAttributeMaxDynamicSharedMemorySize, SM_A);
    cudaFuncSetAttribute(convB, cudaFuncAttributeMaxDynamicSharedMemorySize, SM_B);
    cudaFuncSetAttribute(attn_kernel, cudaFuncAttributeMaxDynamicSharedMemorySize, SM_C);

    convA<<<KEY_A_BLKS + QRY_A_BLKS, 128, SM_A>>>(
        keys, kw1, kb1, p_k1, queries, qw1, qb1, p_q1);
    convB<<<KEY_B_BLKS + QRY_B_BLKS, 128, SM_B>>>(
        p_k1, kw2, kb2, p_k, p_q1, qw2, qb2, qw3, qb3, p_q);
    attn_kernel<<<dim3(T1 / 32, B), 256, SM_C>>>(p_q, p_k, prior, out);
}

// round 5
// speedup vs baseline: 1.0203x; 1.0203x over previous
#include <cuda_runtime.h>
#include <math.h>

// ---------------- problem constants ----------------
#define B    16
#define T1   800
#define T2   200
#define CATT 80

typedef unsigned long long u64;

__device__ __forceinline__ u64 pk2(float lo, float hi) {
    u64 r; asm("mov.b64 %0,{%1,%2};" : "=l"(r) : "f"(lo), "f"(hi)); return r;
}
__device__ __forceinline__ void upk2(u64 v, float& lo, float& hi) {
    asm("mov.b64 {%0,%1},%2;" : "=f"(lo), "=f"(hi) : "l"(v));
}
__device__ __forceinline__ void ffma2(u64& d, u64 a, u64 b) {
    asm("fma.rn.f32x2 %0,%1,%2,%0;" : "+l"(d) : "l"(a), "l"(b));
}

// ---------------- scratch ----------------
__device__ float g_k1[B * 512 * T2];   // key conv1 out
__device__ float g_k [B * CATT * T2];  // key encoder out
__device__ float g_q1[B * 160 * T1];   // query conv1 out
__device__ float g_q [B * CATT * T1];  // query encoder out

// ============================================================
// k=3 conv body, pad=1, f32x2, double-buffered, CK=8.
// 128 threads, micro 4co x 8t:  (TCO/4)*(TT/8) == 128.
// X stored twice in smem (normal + shifted by 1) so both even and
// odd t-pairs are 8/16B-aligned -> zero packing movs in inner loop.
// ============================================================
template<int TCO, int TT, int CIN, int RELU>
__device__ __forceinline__ void conv3_body(
    const float* __restrict__ xb,   // x + b*CIN*T
    const float* __restrict__ w,    // (COUT, CIN, 3)
    const float* __restrict__ bias,
    float* __restrict__ yb,         // y + b*COUT*T
    int T, int co0, int t0, int tid, char* smraw)
{
    constexpr int CK   = 8;
    constexpr int XROW = TT + 4;               // multiple of 4 -> rows 16B aligned
    constexpr int WROW = CK * 3 + 1;           // 25 float2; odd stride helps banks
    constexpr int NC   = CIN / CK;
    constexpr int TTHR = TT / 8;
    constexpr int XTOT = CK * (TT + 2);
    constexpr int WTOT = TCO * CK * 3;         // scalars per chunk
    constexpr int XLD  = (XTOT + 127) / 128;
    constexpr int WLD  = WTOT / 128;
    static_assert((TCO / 4) * TTHR == 128, "layout");
    static_assert(WTOT % 128 == 0, "wld");
    static_assert((XROW * 4) % 16 == 0, "xrow align");

    float*  Xe = (float*)smraw;                                    // 2*CK*XROW
    float*  Xo = Xe + 2 * CK * XROW;                               // 2*CK*XROW
    float2* Ws = (float2*)(Xo + 2 * CK * XROW);                    // 2*TCO*WROW

    const int ci = tid / TTHR;   // 0..TCO/4-1
    const int tj = tid % TTHR;

    u64 acc[4][4];
    #pragma unroll
    for (int i = 0; i < 4; i++)
        #pragma unroll
        for (int p = 0; p < 4; p++) acc[i][p] = 0ull;

    float xr_[XLD], wr_[WLD];

    // prefetch chunk 0
    #pragma unroll
    for (int i = 0; i < XLD; i++) {
        int e = tid + i * 128;
        if (e < XTOT) {
            int r = e / (TT + 2), cc = e % (TT + 2);
            int t = t0 + cc - 1;
            xr_[i] = (t >= 0 && t < T) ? xb[(size_t)r * T + t] : 0.f;
        }
    }
    #pragma unroll
    for (int i = 0; i < WLD; i++) {
        int e = tid + i * 128;
        int r = e / (CK * 3), cc = e % (CK * 3);
        wr_[i] = w[(size_t)(co0 + r) * (CIN * 3) + cc];
    }
    #pragma unroll
    for (int i = 0; i < XLD; i++) {
        int e = tid + i * 128;
        if (e < XTOT) {
            int r = e / (TT + 2), cc = e % (TT + 2);
            Xe[r * XROW + cc] = xr_[i];
            if (cc > 0) Xo[r * XROW + cc - 1] = xr_[i];
        }
    }
    #pragma unroll
    for (int i = 0; i < WLD; i++) {
        int e = tid + i * 128;
        int r = e / (CK * 3), cc = e % (CK * 3);
        Ws[r * WROW + cc] = make_float2(wr_[i], wr_[i]);
    }
    __syncthreads();

    for (int c = 0; c < NC; c++) {
        if (c + 1 < NC) {
            const int c0 = (c + 1) * CK;
            #pragma unroll
            for (int i = 0; i < XLD; i++) {
                int e = tid + i * 128;
                if (e < XTOT) {
                    int r = e / (TT + 2), cc = e % (TT + 2);
                    int t = t0 + cc - 1;
                    xr_[i] = (t >= 0 && t < T) ? xb[(size_t)(c0 + r) * T + t] : 0.f;
                }
            }
            #pragma unroll
            for (int i = 0; i < WLD; i++) {
                int e = tid + i * 128;
                int r = e / (CK * 3), cc = e % (CK * 3);
                wr_[i] = w[(size_t)(co0 + r) * (CIN * 3) + (size_t)c0 * 3 + cc];
            }
        }
        const float*  Xe_ = Xe + (c & 1) * CK * XROW;
        const float*  Xo_ = Xo + (c & 1) * CK * XROW;
        const float2* W   = Ws + (c & 1) * TCO * WROW;
        #pragma unroll
        for (int ck = 0; ck < CK; ck++) {
            const float* pe = Xe_ + ck * XROW + tj * 8;
            const float* po = Xo_ + ck * XROW + tj * 8;
            ulonglong2 E01 = *(const ulonglong2*)pe;        // (x0,x1) (x2,x3)
            ulonglong2 E23 = *(const ulonglong2*)(pe + 4);  // (x4,x5) (x6,x7)
            u64        e4  = *(const u64*)(pe + 8);         // (x8,x9)
            ulonglong2 O01 = *(const ulonglong2*)po;        // (x1,x2) (x3,x4)
            ulonglong2 O23 = *(const ulonglong2*)(po + 4);  // (x5,x6) (x7,x8)
            #pragma unroll
            for (int i = 0; i < 4; i++) {
                const u64* wp = (const u64*)(W + (size_t)(ci * 4 + i) * WROW + ck * 3);
                u64 w0 = wp[0], w1 = wp[1], w2 = wp[2];
                ffma2(acc[i][0], E01.x, w0); ffma2(acc[i][1], E01.y, w0);
                ffma2(acc[i][2], E23.x, w0); ffma2(acc[i][3], E23.y, w0);
                ffma2(acc[i][0], O01.x, w1); ffma2(acc[i][1], O01.y, w1);
                ffma2(acc[i][2], O23.x, w1); ffma2(acc[i][3], O23.y, w1);
                ffma2(acc[i][0], E01.y, w2); ffma2(acc[i][1], E23.x, w2);
                ffma2(acc[i][2], E23.y, w2); ffma2(acc[i][3], e4,    w2);
            }
        }
        if (c + 1 < NC) {
            __syncthreads();
            float*  Xed = Xe + ((c + 1) & 1) * CK * XROW;
            float*  Xod = Xo + ((c + 1) & 1) * CK * XROW;
            float2* Wd  = Ws + ((c + 1) & 1) * TCO * WROW;
            #pragma unroll
            for (int i = 0; i < XLD; i++) {
                int e = tid + i * 128;
                if (e < XTOT) {
                    int r = e / (TT + 2), cc = e % (TT + 2);
                    Xed[r * XROW + cc] = xr_[i];
                    if (cc > 0) Xod[r * XROW + cc - 1] = xr_[i];
                }
            }
            #pragma unroll
            for (int i = 0; i < WLD; i++) {
                int e = tid + i * 128;
                int r = e / (CK * 3), cc = e % (CK * 3);
                Wd[r * WROW + cc] = make_float2(wr_[i], wr_[i]);
            }
            __syncthreads();
        }
    }

    #pragma unroll
    for (int i = 0; i < 4; i++) {
        int co = co0 + ci * 4 + i;
        float bb = bias[co];
        float v[8];
        #pragma unroll
        for (int p = 0; p < 4; p++) upk2(acc[i][p], v[2 * p], v[2 * p + 1]);
        #pragma unroll
        for (int j = 0; j < 8; j++) {
            int t = t0 + tj * 8 + j;
            if (t < T) {
                float o = v[j] + bb;
                if (RELU) o = fmaxf(o, 0.f);
                yb[(size_t)co * T + t] = o;
            }
        }
    }
}

// ---- kernel A: key conv1 (256->512 k3, TCO=64/TT=64) + query conv1 (80->160 k3) ----
#define KEY_A_BLKS (8 * 4 * B)     // 512: 8 co-tiles(64) x 4 t-tiles(64)
#define QRY_A_BLKS (5 * 7 * B)     // 560: 5 co-tiles(32) x 7 t-tiles(128)
__global__ __launch_bounds__(128, 3) void convA(
    const float* __restrict__ keys, const float* __restrict__ kw1,
    const float* __restrict__ kb1, float* __restrict__ k1out,
    const float* __restrict__ qsrc, const float* __restrict__ qw1,
    const float* __restrict__ qb1, float* __restrict__ q1out)
{
    extern __shared__ char sm[];
    const int bid = blockIdx.x, tid = threadIdx.x;
    if (bid < KEY_A_BLKS) {
        int b = bid / 32, r = bid % 32;
        int co0 = (r / 4) * 64, t0 = (r % 4) * 64;
        conv3_body<64, 64, 256, 1>(keys + (size_t)b * 256 * T2, kw1, kb1,
                                   k1out + (size_t)b * 512 * T2, T2, co0, t0, tid, sm);
    } else {
        int qb = bid - KEY_A_BLKS;
        int b = qb / 35, r = qb % 35;
        int co0 = (r / 7) * 32, t0 = (r % 7) * 128;
        conv3_body<32, 128, 80, 1>(qsrc + (size_t)b * 80 * T1, qw1, qb1,
                                   q1out + (size_t)b * 160 * T1, T1, co0, t0, tid, sm);
    }
}

// ============================================================
// k=1 accumulate body: 80 couts x 64 t tile, micro 5co x 8t, CK=16.
// 128 threads: ci=tid/8 (16 -> 5co each), tj=tid%8 (8t each).
// ============================================================
template<int CIN>
__device__ __forceinline__ void k1_accum(
    const float* __restrict__ xb, int T, int t0,
    const float* __restrict__ w,   // (80, CIN)
    float* Xs, float2* Ws, u64 (&acc)[5][4], int tid)
{
    constexpr int CK = 16, XROW = 68, WROW = 17;
    constexpr int NC = CIN / CK;
    constexpr int WLD = 80 * CK / 128;   // 10
    constexpr int XLD = CK * 64 / 128;   // 8
    const int ci = tid >> 3, tj = tid & 7;

    float wr_[WLD], xr_[XLD];
    #pragma unroll
    for (int i = 0; i < WLD; i++) {
        int e = tid + i * 128; int r = e / CK, cc = e % CK;
        wr_[i] = w[(size_t)r * CIN + cc];
    }
    #pragma unroll
    for (int i = 0; i < XLD; i++) {
        int e = tid + i * 128; int r = e / 64, cc = e % 64;
        int t = t0 + cc;
        xr_[i] = (t < T) ? xb[(size_t)r * T + t] : 0.f;
    }
    #pragma unroll
    for (int i = 0; i < WLD; i++) {
        int e = tid + i * 128; int r = e / CK, cc = e % CK;
        Ws[r * WROW + cc] = make_float2(wr_[i], wr_[i]);
    }
    #pragma unroll
    for (int i = 0; i < XLD; i++) {
        int e = tid + i * 128; int r = e / 64, cc = e % 64;
        Xs[r * XROW + cc] = xr_[i];
    }
    __syncthreads();

    for (int c = 0; c < NC; c++) {
        if (c + 1 < NC) {
            const int c0 = (c + 1) * CK;
            #pragma unroll
            for (int i = 0; i < WLD; i++) {
                int e = tid + i * 128; int r = e / CK, cc = e % CK;
                wr_[i] = w[(size_t)r * CIN + c0 + cc];
            }
            #pragma unroll
            for (int i = 0; i < XLD; i++) {
                int e = tid + i * 128; int r = e / 64, cc = e % 64;
                int t = t0 + cc;
                xr_[i] = (t < T) ? xb[(size_t)(c0 + r) * T + t] : 0.f;
            }
        }
        const float*  X = Xs + (c & 1) * CK * XROW;
        const float2* W = Ws + (c & 1) * 80 * WROW;
        #pragma unroll
        for (int ck = 0; ck < CK; ck++) {
            const ulonglong2* xp = (const ulonglong2*)(X + ck * XROW + tj * 8);
            ulonglong2 A = xp[0], Bv = xp[1];
            #pragma unroll
            for (int i = 0; i < 5; i++) {
                u64 wv = *(const u64*)(W + (size_t)(ci * 5 + i) * WROW + ck);
                ffma2(acc[i][0], A.x,  wv); ffma2(acc[i][1], A.y,  wv);
                ffma2(acc[i][2], Bv.x, wv); ffma2(acc[i][3], Bv.y, wv);
            }
        }
        if (c + 1 < NC) {
            __syncthreads();
            float*  Xd = Xs + ((c + 1) & 1) * CK * XROW;
            float2* Wd = Ws + ((c + 1) & 1) * 80 * WROW;
            #pragma unroll
            for (int i = 0; i < WLD; i++) {
                int e = tid + i * 128; int r = e / CK, cc = e % CK;
                Wd[r * WROW + cc] = make_float2(wr_[i], wr_[i]);
            }
            #pragma unroll
            for (int i = 0; i < XLD; i++) {
                int e = tid + i * 128; int r = e / 64, cc = e % 64;
                Xd[r * XROW + cc] = xr_[i];
            }
            __syncthreads();
        }
    }
}

// ---- kernel B: key conv2 (512->80 k1) + fused query conv2+3 ----
#define KEY_B_BLKS (4 * B)     // 64: 4 t-tiles(64)
#define QRY_B_BLKS (13 * B)    // 208: 13 t-tiles(64)
#define HROW 68
__global__ __launch_bounds__(128, 3) void convB(
    const float* __restrict__ k1in, const float* __restrict__ kw2,
    const float* __restrict__ kb2, float* __restrict__ kout,
    const float* __restrict__ q1in,
    const float* __restrict__ qw2, const float* __restrict__ qb2,
    const float* __restrict__ qw3, const float* __restrict__ qb3,
    float* __restrict__ qout)
{
    extern __shared__ char sm[];
    float*  Xs  = (float*)sm;                              // 2*16*68
    float2* Ws  = (float2*)(sm + 2 * 16 * 68 * 4);         // 2*80*17
    float*  Hs  = (float*)((char*)Ws + 2 * 80 * 17 * 8);   // 80*68
    float*  W3s = Hs + 80 * HROW;                          // 80*80

    const int bid = blockIdx.x, tid = threadIdx.x;
    const int ci = tid >> 3, tj = tid & 7;

    u64 acc[5][4];
    #pragma unroll
    for (int i = 0; i < 5; i++)
        #pragma unroll
        for (int p = 0; p < 4; p++) acc[i][p] = 0ull;

    if (bid < KEY_B_BLKS) {
        int b = bid / 4, t0 = (bid % 4) * 64;
        k1_accum<512>(k1in + (size_t)b * 512 * T2, T2, t0, kw2, Xs, Ws, acc, tid);
        float* yb = kout + (size_t)b * 80 * T2;
        #pragma unroll
        for (int i = 0; i < 5; i++) {
            int co = ci * 5 + i;
            float bb = kb2[co];
            float v[8];
            #pragma unroll
            for (int p = 0; p < 4; p++) upk2(acc[i][p], v[2 * p], v[2 * p + 1]);
            #pragma unroll
            for (int j = 0; j < 8; j++) {
                int t = t0 + tj * 8 + j;
                if (t < T2) yb[(size_t)co * T2 + t] = v[j] + bb;
            }
        }
    } else {
        int qb = bid - KEY_B_BLKS;
        int b = qb / 13, t0 = (qb % 13) * 64;
        // preload W3 (plain floats)
        for (int e = tid; e < 6400; e += 128) W3s[e] = qw3[e];
        k1_accum<160>(q1in + (size_t)b * 160 * T1, T1, t0, qw2, Xs, Ws, acc, tid);
        // h = relu(acc + b2) -> Hs
        #pragma unroll
        for (int i = 0; i < 5; i++) {
            int co = ci * 5 + i;
            float bb = qb2[co];
            float v[8];
            #pragma unroll
            for (int p = 0; p < 4; p++) upk2(acc[i][p], v[2 * p], v[2 * p + 1]);
            float4 h0, h1;
            h0.x = fmaxf(v[0] + bb, 0.f); h0.y = fmaxf(v[1] + bb, 0.f);
            h0.z = fmaxf(v[2] + bb, 0.f); h0.w = fmaxf(v[3] + bb, 0.f);
            h1.x = fmaxf(v[4] + bb, 0.f); h1.y = fmaxf(v[5] + bb, 0.f);
            h1.z = fmaxf(v[6] + bb, 0.f); h1.w = fmaxf(v[7] + bb, 0.f);
            *(float4*)(Hs + (size_t)co * HROW + tj * 8) = h0;
            *(float4*)(Hs + (size_t)co * HROW + tj * 8 + 4) = h1;
        }
        __syncthreads();

        u64 acc2[5][4];
        #pragma unroll
        for (int i = 0; i < 5; i++)
            #pragma unroll
            for (int p = 0; p < 4; p++) acc2[i][p] = 0ull;

        #pragma unroll 4
        for (int ck = 0; ck < 80; ck++) {
            const ulonglong2* xp = (const ulonglong2*)(Hs + (size_t)ck * HROW + tj * 8);
            ulonglong2 A = xp[0], Bv = xp[1];
            #pragma unroll
            for (int i = 0; i < 5; i++) {
                float wv = W3s[(size_t)(ci * 5 + i) * 80 + ck];
                u64 wp = pk2(wv, wv);
                ffma2(acc2[i][0], A.x,  wp); ffma2(acc2[i][1], A.y,  wp);
                ffma2(acc2[i][2], Bv.x, wp); ffma2(acc2[i][3], Bv.y, wp);
            }
        }

        float* yb = qout + (size_t)b * 80 * T1;
        #pragma unroll
        for (int i = 0; i < 5; i++) {
            int co = ci * 5 + i;
            float bb = qb3[co];
            float v[8];
            #pragma unroll
            for (int p = 0; p < 4; p++) upk2(acc2[i][p], v[2 * p], v[2 * p + 1]);
            #pragma unroll
            for (int j = 0; j < 8; j++) {
                int t = t0 + tj * 8 + j;
                if (t < T1) yb[(size_t)co * T1 + t] = v[j] + bb;
            }
        }
    }
}

// ============================================================
// Attention: dist -> log_softmax over T2 -> + log(prior+1e-8)
// ============================================================
#define KROW 224
__global__ __launch_bounds__(256) void attn_kernel(
    const float* __restrict__ q, const float* __restrict__ k,
    const float* __restrict__ prior, float* __restrict__ out)
{
    extern __shared__ float smf[];
    float* ks  = smf;                // 80 * 224
    float* qs  = ks + 80 * KROW;     // 80 * 32
    float* k2s = qs + 80 * 32;       // 224
    float* q2s = k2s + KROW;         // 32

    const int b   = blockIdx.y;
    const int t10 = blockIdx.x * 32;
    const int tid = threadIdx.x;

    const float* kb = k + (size_t)b * CATT * T2;
    const float* qb = q + (size_t)b * CATT * T1;

    for (int idx = tid; idx < 80 * KROW; idx += 256) {
        int c = idx / KROW, t = idx % KROW;
        ks[idx] = (t < T2) ? kb[(size_t)c * T2 + t] : 0.f;
    }
    for (int idx = tid; idx < 80 * 32; idx += 256) {
        int c = idx / 32, i = idx % 32;
        qs[idx] = qb[(size_t)c * T1 + t10 + i];
    }
    __syncthreads();

    if (tid < KROW) {
        float s = 0.f;
        #pragma unroll 8
        for (int c = 0; c < 80; c++) { float v = ks[c * KROW + tid]; s += v * v; }
        k2s[tid] = s;
    } else {
        int i = tid - KROW;
        if (i < 32) {
            float s = 0.f;
            #pragma unroll 8
            for (int c = 0; c < 80; c++) { float v = qs[c * 32 + i]; s += v * v; }
            q2s[i] = s;
        }
    }
    __syncthreads();

    const int warp = tid / 32;
    const int lane = tid % 32;

    u64 dp[2][7];
    #pragma unroll
    for (int p = 0; p < 2; p++)
        #pragma unroll
        for (int j = 0; j < 7; j++) dp[p][j] = 0ull;

    #pragma unroll 4
    for (int c = 0; c < 80; c++) {
        const ulonglong2* qp = (const ulonglong2*)&qs[c * 32 + warp * 4];
        ulonglong2 qv = qp[0];
        #pragma unroll
        for (int j = 0; j < 7; j++) {
            float kv = ks[c * KROW + lane + 32 * j];
            u64 kp = pk2(kv, kv);
            ffma2(dp[0][j], qv.x, kp);
            ffma2(dp[1][j], qv.y, kp);
        }
    }

    float dot[4][7];
    #pragma unroll
    for (int p = 0; p < 2; p++)
        #pragma unroll
        for (int j = 0; j < 7; j++) upk2(dp[p][j], dot[2 * p][j], dot[2 * p + 1][j]);

    const bool last_valid = (lane + 192) < T2;

    #pragma unroll
    for (int i = 0; i < 4; i++) {
        int r  = warp * 4 + i;
        int t1 = t10 + r;
        float q2 = q2s[r];
        float xv[7];
        #pragma unroll
        for (int j = 0; j < 7; j++) {
            int t2 = lane + 32 * j;
            bool valid = (j < 6) || last_valid;
            xv[j] = valid ? (-0.0005f * (q2 + k2s[t2] - 2.f * dot[i][j])) : -1e30f;
        }
        float m = xv[0];
        #pragma unroll
        for (int j = 1; j < 7; j++) m = fmaxf(m, xv[j]);
        #pragma unroll
        for (int off = 16; off; off >>= 1)
            m = fmaxf(m, __shfl_xor_sync(0xFFFFFFFFu, m, off));
        float s = 0.f;
        #pragma unroll
        for (int j = 0; j < 7; j++) {
            bool valid = (j < 6) || last_valid;
            if (valid) s += __expf(xv[j] - m);
        }
        #pragma unroll
        for (int off = 16; off; off >>= 1)
            s += __shfl_xor_sync(0xFFFFFFFFu, s, off);
        float lse = m + __logf(s);

        const float* pr = prior + ((size_t)b * T1 + t1) * T2;
        float* ob = out + ((size_t)b * T1 + t1) * T2;
        #pragma unroll
        for (int j = 0; j < 7; j++) {
            int t2 = lane + 32 * j;
            bool valid = (j < 6) || last_valid;
            if (valid)
                ob[t2] = xv[j] - lse + __logf(pr[t2] + 1e-8f);
        }
    }
}

// ============================================================
// launch
// ============================================================
extern "C" void kernel_launch(void* const* d_in, const int* in_sizes, int n_in,
                              void* d_out, int out_size)
{
    const float* queries = (const float*)d_in[0];
    const float* keys    = (const float*)d_in[1];
    const float* prior   = (const float*)d_in[2];
    const float* kw1 = (const float*)d_in[3];
    const float* kb1 = (const float*)d_in[4];
    const float* kw2 = (const float*)d_in[5];
    const float* kb2 = (const float*)d_in[6];
    const float* qw1 = (const float*)d_in[7];
    const float* qb1 = (const float*)d_in[8];
    const float* qw2 = (const float*)d_in[9];
    const float* qb2 = (const float*)d_in[10];
    const float* qw3 = (const float*)d_in[11];
    const float* qb3 = (const float*)d_in[12];
    float* out = (float*)d_out;

    float *p_k1, *p_k, *p_q1, *p_q;
    cudaGetSymbolAddress((void**)&p_k1, g_k1);
    cudaGetSymbolAddress((void**)&p_k,  g_k);
    cudaGetSymbolAddress((void**)&p_q1, g_q1);
    cudaGetSymbolAddress((void**)&p_q,  g_q);

    // smem sizes
    // A key : Xe+Xo 2*(2*8*68*4)=8704  + W 2*64*25*8=25600  -> 34304
    // A qry : Xe+Xo 2*(2*8*132*4)=16896 + W 2*32*25*8=12800 -> 29696
    const int SM_A = 34304;
    // B: Xs 2*16*68*4 + Ws 2*80*17*8 + Hs 80*68*4 + W3 80*80*4
    const int SM_B = 2 * 16 * 68 * 4 + 2 * 80 * 17 * 8 + 80 * HROW * 4 + 6400 * 4; // 77824
    const int SM_C = (80 * KROW + 80 * 32 + KROW + 32) * 4;         // 82944

    cudaFuncSetAttribute(convA, cudaFuncAttributeMaxDynamicSharedMemorySize, SM_A);
    cudaFuncSetAttribute(convB, cudaFuncAttributeMaxDynamicSharedMemorySize, SM_B);
    cudaFuncSetAttribute(attn_kernel, cudaFuncAttributeMaxDynamicSharedMemorySize, SM_C);

    convA<<<KEY_A_BLKS + QRY_A_BLKS, 128, SM_A>>>(
        keys, kw1, kb1, p_k1, queries, qw1, qb1, p_q1);
    convB<<<KEY_B_BLKS + QRY_B_BLKS, 128, SM_B>>>(
        p_k1, kw2, kb2, p_k, p_q1, qw2, qb2, qw3, qb3, p_q);
    attn_kernel<<<dim3(T1 / 32, B), 256, SM_C>>>(p_q, p_k, prior, out);
}

// round 6
// speedup vs baseline: 1.3167x; 1.2906x over previous
#include <cuda_runtime.h>
#include <math.h>

// ---------------- problem constants ----------------
#define B    16
#define T1   800
#define T2   200
#define CATT 80

typedef unsigned long long u64;

__device__ __forceinline__ u64 pk2(float lo, float hi) {
    u64 r; asm("mov.b64 %0,{%1,%2};" : "=l"(r) : "f"(lo), "f"(hi)); return r;
}
__device__ __forceinline__ void upk2(u64 v, float& lo, float& hi) {
    asm("mov.b64 {%0,%1},%2;" : "=f"(lo), "=f"(hi) : "l"(v));
}
__device__ __forceinline__ void ffma2(u64& d, u64 a, u64 b) {
    asm("fma.rn.f32x2 %0,%1,%2,%0;" : "+l"(d) : "l"(a), "l"(b));
}
__device__ __forceinline__ void cpa16(unsigned dst, const void* src) {
    asm volatile("cp.async.cg.shared.global [%0], [%1], 16;\n"
                 :: "r"(dst), "l"(src) : "memory");
}
#define CPA_COMMIT() asm volatile("cp.async.commit_group;\n" ::: "memory")
#define CPA_WAIT0()  asm volatile("cp.async.wait_group 0;\n" ::: "memory")

// ---------------- scratch ----------------
__device__ float g_k1[B * 512 * T2];   // key conv1 out
__device__ float g_k [B * CATT * T2];  // key encoder out
__device__ float g_q1[B * 160 * T1];   // query conv1 out
__device__ float g_q [B * CATT * T1];  // query encoder out

// pair-packed weights: [chunk c][co-pair][ck 0..7][tap 0..2] u64 = (w[2p], w[2p+1])
#define KW1P_N (32 * 256 * 24)   // 196608
#define QW1P_N (10 * 80 * 24)    // 19200
__device__ alignas(16) u64 g_kw1p[KW1P_N];
__device__ alignas(16) u64 g_qw1p[QW1P_N];

// ============================================================
// one-time weight pair-packing
// ============================================================
__global__ void prep_w(const float* __restrict__ kw1, const float* __restrict__ qw1)
{
    int idx = blockIdx.x * 256 + threadIdx.x;
    if (idx < KW1P_N) {
        int k  = idx % 3;
        int ck = (idx / 3) & 7;
        int p  = (idx / 24) & 255;
        int c  = idx / (24 * 256);
        int cin = c * 8 + ck;
        g_kw1p[idx] = pk2(kw1[(size_t)(2 * p) * 768 + cin * 3 + k],
                          kw1[(size_t)(2 * p + 1) * 768 + cin * 3 + k]);
    } else if (idx < KW1P_N + QW1P_N) {
        int j  = idx - KW1P_N;
        int k  = j % 3;
        int ck = (j / 3) & 7;
        int p  = (j / 24) % 80;
        int c  = j / (24 * 80);
        int cin = c * 8 + ck;
        g_qw1p[j] = pk2(qw1[(size_t)(2 * p) * 240 + cin * 3 + k],
                        qw1[(size_t)(2 * p + 1) * 240 + cin * 3 + k]);
    }
}

// ============================================================
// k=3 conv body, pad=1. 64 threads, micro 8co(4 pairs) x 8t(2 groups of 4).
// X stored dup (x,x) u64 in smem; W pair-packed via cp.async.
// ============================================================
template<int TCO, int TT, int CIN, int RELU, int NPG>
__device__ __forceinline__ void conv3_pair(
    const float* __restrict__ xb,   // x + b*CIN*T
    const u64*  __restrict__ wp,    // pair-packed weights
    const float* __restrict__ bias,
    float* __restrict__ yb,         // y + b*COUT*T
    int T, int co0, int t0, int tid, char* sm)
{
    constexpr int CK    = 8;
    constexpr int NC    = CIN / CK;
    constexpr int TTHR  = TT / 8;
    constexpr int COTHR = TCO / 8;
    static_assert(COTHR * TTHR == 64, "layout");
    constexpr int XCOLS = TT + 2;             // even -> rows 16B aligned
    constexpr int XTOT  = CK * XCOLS;
    constexpr int XLD   = (XTOT + 63) / 64;
    constexpr int NP    = TCO / 2;            // pairs per tile
    constexpr int WOPS  = NP * 12;            // 16B cp.async per chunk
    constexpr int WLD   = WOPS / 64;
    static_assert(WOPS % 64 == 0, "wops");
    constexpr int WPAD  = 26;                 // u64 per pair row (24 + pad)
    constexpr int H     = TT / 2;

    u64* Xd = (u64*)sm;                       // 2 * CK * XCOLS
    u64* Ws = Xd + 2 * CK * XCOLS;            // 2 * NP * WPAD

    const int ci = tid / TTHR;                // 0..COTHR-1
    const int tj = tid % TTHR;

    u64 acc[4][8];
    #pragma unroll
    for (int i = 0; i < 4; i++)
        #pragma unroll
        for (int j = 0; j < 8; j++) acc[i][j] = 0ull;

    float xr[XLD];

    // ---- X stage (LDG -> regs) ----
    auto ldgX = [&](int c) {
        #pragma unroll
        for (int i = 0; i < XLD; i++) {
            int e = tid + i * 64;
            float v = 0.f;
            if (e < XTOT) {
                int r = e / XCOLS, col = e % XCOLS;
                int t = t0 + col - 1;
                if (t >= 0 && t < T) v = xb[(size_t)(c * CK + r) * T + t];
            }
            xr[i] = v;
        }
    };
    auto stsX = [&](int buf) {
        u64* Xb = Xd + buf * CK * XCOLS;
        #pragma unroll
        for (int i = 0; i < XLD; i++) {
            int e = tid + i * 64;
            if (e < XTOT) Xb[e] = pk2(xr[i], xr[i]);
        }
    };
    auto cpaW = [&](int c, int buf) {
        const char* slab = (const char*)(wp + ((size_t)c * NPG + (co0 >> 1)) * 24);
        unsigned wbs = (unsigned)__cvta_generic_to_shared(Ws + buf * NP * WPAD);
        #pragma unroll
        for (int i = 0; i < WLD; i++) {
            int e = tid + i * 64;
            int p = e / 12, o = e % 12;
            cpa16(wbs + p * (WPAD * 8) + o * 16, slab + p * 192 + o * 16);
        }
        CPA_COMMIT();
    };

    // prologue: chunk 0
    cpaW(0, 0);
    ldgX(0);
    stsX(0);
    CPA_WAIT0();
    __syncthreads();

    for (int c = 0; c < NC; c++) {
        if (c + 1 < NC) {
            cpaW(c + 1, (c + 1) & 1);
            ldgX(c + 1);
        }
        // compute chunk c
        {
            const u64* X = Xd + (c & 1) * CK * XCOLS;
            const u64* W = Ws + (c & 1) * NP * WPAD;
            #pragma unroll
            for (int ck = 0; ck < CK; ck++) {
                const u64* xrow = X + ck * XCOLS;
                ulonglong2 a0 = *(const ulonglong2*)(xrow + tj * 4);
                ulonglong2 a1 = *(const ulonglong2*)(xrow + tj * 4 + 2);
                ulonglong2 a2 = *(const ulonglong2*)(xrow + tj * 4 + 4);
                ulonglong2 b0 = *(const ulonglong2*)(xrow + tj * 4 + H);
                ulonglong2 b1 = *(const ulonglong2*)(xrow + tj * 4 + H + 2);
                ulonglong2 b2 = *(const ulonglong2*)(xrow + tj * 4 + H + 4);
                u64 d[6] = {a0.x, a0.y, a1.x, a1.y, a2.x, a2.y};
                u64 e2[6] = {b0.x, b0.y, b1.x, b1.y, b2.x, b2.y};
                #pragma unroll
                for (int i = 0; i < 4; i++) {
                    const u64* wr = W + (size_t)(ci * 4 + i) * WPAD + ck * 3;
                    u64 w0 = wr[0], w1 = wr[1], w2 = wr[2];
                    #pragma unroll
                    for (int j = 0; j < 4; j++) {
                        ffma2(acc[i][j], d[j],      w0);
                        ffma2(acc[i][j], d[j + 1],  w1);
                        ffma2(acc[i][j], d[j + 2],  w2);
                        ffma2(acc[i][4 + j], e2[j],     w0);
                        ffma2(acc[i][4 + j], e2[j + 1], w1);
                        ffma2(acc[i][4 + j], e2[j + 2], w2);
                    }
                }
            }
        }
        if (c + 1 < NC) {
            stsX((c + 1) & 1);
            CPA_WAIT0();
            __syncthreads();
        }
    }

    // epilogue
    #pragma unroll
    for (int i = 0; i < 4; i++) {
        int coA = co0 + (ci * 4 + i) * 2;
        int coB = coA + 1;
        float bA = bias[coA], bB = bias[coB];
        #pragma unroll
        for (int g = 0; g < 2; g++) {
            int t = t0 + tj * 4 + g * H;
            if (t < T) {
                float a0, c0, a1, c1, a2, c2, a3, c3;
                upk2(acc[i][g * 4 + 0], a0, c0);
                upk2(acc[i][g * 4 + 1], a1, c1);
                upk2(acc[i][g * 4 + 2], a2, c2);
                upk2(acc[i][g * 4 + 3], a3, c3);
                float4 fA = make_float4(a0 + bA, a1 + bA, a2 + bA, a3 + bA);
                float4 fB = make_float4(c0 + bB, c1 + bB, c2 + bB, c3 + bB);
                if (RELU) {
                    fA.x = fmaxf(fA.x, 0.f); fA.y = fmaxf(fA.y, 0.f);
                    fA.z = fmaxf(fA.z, 0.f); fA.w = fmaxf(fA.w, 0.f);
                    fB.x = fmaxf(fB.x, 0.f); fB.y = fmaxf(fB.y, 0.f);
                    fB.z = fmaxf(fB.z, 0.f); fB.w = fmaxf(fB.w, 0.f);
                }
                *(float4*)(yb + (size_t)coA * T + t) = fA;
                *(float4*)(yb + (size_t)coB * T + t) = fB;
            }
        }
    }
}

// ---- kernel A: key conv1 (256->512 k3) + query conv1 (80->160 k3) ----
#define KEY_A_BLKS (4 * 7 * B)     // 448: 4 co-tiles(128) x 7 t-tiles(32)
#define QRY_A_BLKS (5 * 7 * B)     // 560: 5 co-tiles(32)  x 7 t-tiles(128)
__global__ __launch_bounds__(64, 6) void convA(
    const float* __restrict__ keys, const float* __restrict__ kb1,
    float* __restrict__ k1out,
    const float* __restrict__ qsrc, const float* __restrict__ qb1,
    float* __restrict__ q1out)
{
    extern __shared__ char sm[];
    const int bid = blockIdx.x, tid = threadIdx.x;
    if (bid < KEY_A_BLKS) {
        int b = bid / 28, r = bid % 28;
        int co0 = (r / 7) * 128, t0 = (r % 7) * 32;
        conv3_pair<128, 32, 256, 1, 256>(keys + (size_t)b * 256 * T2, g_kw1p, kb1,
                                         k1out + (size_t)b * 512 * T2, T2, co0, t0, tid, sm);
    } else {
        int qb = bid - KEY_A_BLKS;
        int b = qb / 35, r = qb % 35;
        int co0 = (r / 7) * 32, t0 = (r % 7) * 128;
        conv3_pair<32, 128, 80, 1, 80>(qsrc + (size_t)b * 80 * T1, g_qw1p, qb1,
                                       q1out + (size_t)b * 160 * T1, T1, co0, t0, tid, sm);
    }
}
// smem: key Xd 2*8*34*8=4352 + Ws 2*64*26*8=26624 -> 30976 ; qry 16640+6656=23296
#define SM_A 30976

// ============================================================
// k=1 accumulate body: 80 couts x 64 t tile, micro 5co x 8t, CK=16.
// 128 threads: ci=tid/8 (16 -> 5co each), tj=tid%8 (8t each).
// ============================================================
template<int CIN>
__device__ __forceinline__ void k1_accum(
    const float* __restrict__ xb, int T, int t0,
    const float* __restrict__ w,   // (80, CIN)
    float* Xs, float2* Ws, u64 (&acc)[5][4], int tid)
{
    constexpr int CK = 16, XROW = 68, WROW = 17;
    constexpr int NC = CIN / CK;
    constexpr int WLD = 80 * CK / 128;   // 10
    constexpr int XLD = CK * 64 / 128;   // 8
    const int ci = tid >> 3, tj = tid & 7;

    float wr_[WLD], xr_[XLD];
    #pragma unroll
    for (int i = 0; i < WLD; i++) {
        int e = tid + i * 128; int r = e / CK, cc = e % CK;
        wr_[i] = w[(size_t)r * CIN + cc];
    }
    #pragma unroll
    for (int i = 0; i < XLD; i++) {
        int e = tid + i * 128; int r = e / 64, cc = e % 64;
        int t = t0 + cc;
        xr_[i] = (t < T) ? xb[(size_t)r * T + t] : 0.f;
    }
    #pragma unroll
    for (int i = 0; i < WLD; i++) {
        int e = tid + i * 128; int r = e / CK, cc = e % CK;
        Ws[r * WROW + cc] = make_float2(wr_[i], wr_[i]);
    }
    #pragma unroll
    for (int i = 0; i < XLD; i++) {
        int e = tid + i * 128; int r = e / 64, cc = e % 64;
        Xs[r * XROW + cc] = xr_[i];
    }
    __syncthreads();

    for (int c = 0; c < NC; c++) {
        if (c + 1 < NC) {
            const int c0 = (c + 1) * CK;
            #pragma unroll
            for (int i = 0; i < WLD; i++) {
                int e = tid + i * 128; int r = e / CK, cc = e % CK;
                wr_[i] = w[(size_t)r * CIN + c0 + cc];
            }
            #pragma unroll
            for (int i = 0; i < XLD; i++) {
                int e = tid + i * 128; int r = e / 64, cc = e % 64;
                int t = t0 + cc;
                xr_[i] = (t < T) ? xb[(size_t)(c0 + r) * T + t] : 0.f;
            }
        }
        const float*  X = Xs + (c & 1) * CK * XROW;
        const float2* W = Ws + (c & 1) * 80 * WROW;
        #pragma unroll
        for (int ck = 0; ck < CK; ck++) {
            const ulonglong2* xp = (const ulonglong2*)(X + ck * XROW + tj * 8);
            ulonglong2 A = xp[0], Bv = xp[1];
            #pragma unroll
            for (int i = 0; i < 5; i++) {
                u64 wv = *(const u64*)(W + (size_t)(ci * 5 + i) * WROW + ck);
                ffma2(acc[i][0], A.x,  wv); ffma2(acc[i][1], A.y,  wv);
                ffma2(acc[i][2], Bv.x, wv); ffma2(acc[i][3], Bv.y, wv);
            }
        }
        if (c + 1 < NC) {
            __syncthreads();
            float*  Xd = Xs + ((c + 1) & 1) * CK * XROW;
            float2* Wd = Ws + ((c + 1) & 1) * 80 * WROW;
            #pragma unroll
            for (int i = 0; i < WLD; i++) {
                int e = tid + i * 128; int r = e / CK, cc = e % CK;
                Wd[r * WROW + cc] = make_float2(wr_[i], wr_[i]);
            }
            #pragma unroll
            for (int i = 0; i < XLD; i++) {
                int e = tid + i * 128; int r = e / 64, cc = e % 64;
                Xd[r * XROW + cc] = xr_[i];
            }
            __syncthreads();
        }
    }
}

// ---- kernel B: key conv2 (512->80 k1) + fused query conv2+3 ----
#define KEY_B_BLKS (4 * B)     // 64
#define QRY_B_BLKS (13 * B)    // 208
#define HROW 68
__global__ __launch_bounds__(128, 3) void convB(
    const float* __restrict__ k1in, const float* __restrict__ kw2,
    const float* __restrict__ kb2, float* __restrict__ kout,
    const float* __restrict__ q1in,
    const float* __restrict__ qw2, const float* __restrict__ qb2,
    const float* __restrict__ qw3, const float* __restrict__ qb3,
    float* __restrict__ qout)
{
    extern __shared__ char sm[];
    float*  Xs  = (float*)sm;                              // 2*16*68
    float2* Ws  = (float2*)(sm + 2 * 16 * 68 * 4);         // 2*80*17
    float*  Hs  = (float*)((char*)Ws + 2 * 80 * 17 * 8);   // 80*68
    float*  W3s = Hs + 80 * HROW;                          // 80*80

    const int bid = blockIdx.x, tid = threadIdx.x;
    const int ci = tid >> 3, tj = tid & 7;

    u64 acc[5][4];
    #pragma unroll
    for (int i = 0; i < 5; i++)
        #pragma unroll
        for (int p = 0; p < 4; p++) acc[i][p] = 0ull;

    if (bid < KEY_B_BLKS) {
        int b = bid / 4, t0 = (bid % 4) * 64;
        k1_accum<512>(k1in + (size_t)b * 512 * T2, T2, t0, kw2, Xs, Ws, acc, tid);
        float* yb = kout + (size_t)b * 80 * T2;
        #pragma unroll
        for (int i = 0; i < 5; i++) {
            int co = ci * 5 + i;
            float bb = kb2[co];
            float v[8];
            #pragma unroll
            for (int p = 0; p < 4; p++) upk2(acc[i][p], v[2 * p], v[2 * p + 1]);
            #pragma unroll
            for (int j = 0; j < 8; j++) {
                int t = t0 + tj * 8 + j;
                if (t < T2) yb[(size_t)co * T2 + t] = v[j] + bb;
            }
        }
    } else {
        int qb = bid - KEY_B_BLKS;
        int b = qb / 13, t0 = (qb % 13) * 64;
        for (int e = tid; e < 6400; e += 128) W3s[e] = qw3[e];
        k1_accum<160>(q1in + (size_t)b * 160 * T1, T1, t0, qw2, Xs, Ws, acc, tid);
        #pragma unroll
        for (int i = 0; i < 5; i++) {
            int co = ci * 5 + i;
            float bb = qb2[co];
            float v[8];
            #pragma unroll
            for (int p = 0; p < 4; p++) upk2(acc[i][p], v[2 * p], v[2 * p + 1]);
            float4 h0, h1;
            h0.x = fmaxf(v[0] + bb, 0.f); h0.y = fmaxf(v[1] + bb, 0.f);
            h0.z = fmaxf(v[2] + bb, 0.f); h0.w = fmaxf(v[3] + bb, 0.f);
            h1.x = fmaxf(v[4] + bb, 0.f); h1.y = fmaxf(v[5] + bb, 0.f);
            h1.z = fmaxf(v[6] + bb, 0.f); h1.w = fmaxf(v[7] + bb, 0.f);
            *(float4*)(Hs + (size_t)co * HROW + tj * 8) = h0;
            *(float4*)(Hs + (size_t)co * HROW + tj * 8 + 4) = h1;
        }
        __syncthreads();

        u64 acc2[5][4];
        #pragma unroll
        for (int i = 0; i < 5; i++)
            #pragma unroll
            for (int p = 0; p < 4; p++) acc2[i][p] = 0ull;

        #pragma unroll 4
        for (int ck = 0; ck < 80; ck++) {
            const ulonglong2* xp = (const ulonglong2*)(Hs + (size_t)ck * HROW + tj * 8);
            ulonglong2 A = xp[0], Bv = xp[1];
            #pragma unroll
            for (int i = 0; i < 5; i++) {
                float wv = W3s[(size_t)(ci * 5 + i) * 80 + ck];
                u64 wpk = pk2(wv, wv);
                ffma2(acc2[i][0], A.x,  wpk); ffma2(acc2[i][1], A.y,  wpk);
                ffma2(acc2[i][2], Bv.x, wpk); ffma2(acc2[i][3], Bv.y, wpk);
            }
        }

        float* yb = qout + (size_t)b * 80 * T1;
        #pragma unroll
        for (int i = 0; i < 5; i++) {
            int co = ci * 5 + i;
            float bb = qb3[co];
            float v[8];
            #pragma unroll
            for (int p = 0; p < 4; p++) upk2(acc2[i][p], v[2 * p], v[2 * p + 1]);
            #pragma unroll
            for (int j = 0; j < 8; j++) {
                int t = t0 + tj * 8 + j;
                if (t < T1) yb[(size_t)co * T1 + t] = v[j] + bb;
            }
        }
    }
}

// ============================================================
// Attention: dist -> log_softmax over T2 -> + log(prior+1e-8)
// ============================================================
#define KROW 224
__global__ __launch_bounds__(256) void attn_kernel(
    const float* __restrict__ q, const float* __restrict__ k,
    const float* __restrict__ prior, float* __restrict__ out)
{
    extern __shared__ float smf[];
    float* ks  = smf;                // 80 * 224
    float* qs  = ks + 80 * KROW;     // 80 * 32
    float* k2s = qs + 80 * 32;       // 224
    float* q2s = k2s + KROW;         // 32

    const int b   = blockIdx.y;
    const int t10 = blockIdx.x * 32;
    const int tid = threadIdx.x;

    const float* kb = k + (size_t)b * CATT * T2;
    const float* qb = q + (size_t)b * CATT * T1;

    for (int idx = tid; idx < 80 * KROW; idx += 256) {
        int c = idx / KROW, t = idx % KROW;
        ks[idx] = (t < T2) ? kb[(size_t)c * T2 + t] : 0.f;
    }
    for (int idx = tid; idx < 80 * 32; idx += 256) {
        int c = idx / 32, i = idx % 32;
        qs[idx] = qb[(size_t)c * T1 + t10 + i];
    }
    __syncthreads();

    if (tid < KROW) {
        float s = 0.f;
        #pragma unroll 8
        for (int c = 0; c < 80; c++) { float v = ks[c * KROW + tid]; s += v * v; }
        k2s[tid] = s;
    } else {
        int i = tid - KROW;
        if (i < 32) {
            float s = 0.f;
            #pragma unroll 8
            for (int c = 0; c < 80; c++) { float v = qs[c * 32 + i]; s += v * v; }
            q2s[i] = s;
        }
    }
    __syncthreads();

    const int warp = tid / 32;
    const int lane = tid % 32;

    u64 dp[2][7];
    #pragma unroll
    for (int p = 0; p < 2; p++)
        #pragma unroll
        for (int j = 0; j < 7; j++) dp[p][j] = 0ull;

    #pragma unroll 4
    for (int c = 0; c < 80; c++) {
        const ulonglong2* qp = (const ulonglong2*)&qs[c * 32 + warp * 4];
        ulonglong2 qv = qp[0];
        #pragma unroll
        for (int j = 0; j < 7; j++) {
            float kv = ks[c * KROW + lane + 32 * j];
            u64 kp = pk2(kv, kv);
            ffma2(dp[0][j], qv.x, kp);
            ffma2(dp[1][j], qv.y, kp);
        }
    }

    float dot[4][7];
    #pragma unroll
    for (int p = 0; p < 2; p++)
        #pragma unroll
        for (int j = 0; j < 7; j++) upk2(dp[p][j], dot[2 * p][j], dot[2 * p + 1][j]);

    const bool last_valid = (lane + 192) < T2;

    #pragma unroll
    for (int i = 0; i < 4; i++) {
        int r  = warp * 4 + i;
        int t1 = t10 + r;
        float q2 = q2s[r];
        float xv[7];
        #pragma unroll
        for (int j = 0; j < 7; j++) {
            int t2 = lane + 32 * j;
            bool valid = (j < 6) || last_valid;
            xv[j] = valid ? (-0.0005f * (q2 + k2s[t2] - 2.f * dot[i][j])) : -1e30f;
        }
        float m = xv[0];
        #pragma unroll
        for (int j = 1; j < 7; j++) m = fmaxf(m, xv[j]);
        #pragma unroll
        for (int off = 16; off; off >>= 1)
            m = fmaxf(m, __shfl_xor_sync(0xFFFFFFFFu, m, off));
        float s = 0.f;
        #pragma unroll
        for (int j = 0; j < 7; j++) {
            bool valid = (j < 6) || last_valid;
            if (valid) s += __expf(xv[j] - m);
        }
        #pragma unroll
        for (int off = 16; off; off >>= 1)
            s += __shfl_xor_sync(0xFFFFFFFFu, s, off);
        float lse = m + __logf(s);

        const float* pr = prior + ((size_t)b * T1 + t1) * T2;
        float* ob = out + ((size_t)b * T1 + t1) * T2;
        #pragma unroll
        for (int j = 0; j < 7; j++) {
            int t2 = lane + 32 * j;
            bool valid = (j < 6) || last_valid;
            if (valid)
                ob[t2] = xv[j] - lse + __logf(pr[t2] + 1e-8f);
        }
    }
}

// ============================================================
// launch
// ============================================================
extern "C" void kernel_launch(void* const* d_in, const int* in_sizes, int n_in,
                              void* d_out, int out_size)
{
    const float* queries = (const float*)d_in[0];
    const float* keys    = (const float*)d_in[1];
    const float* prior   = (const float*)d_in[2];
    const float* kw1 = (const float*)d_in[3];
    const float* kb1 = (const float*)d_in[4];
    const float* kw2 = (const float*)d_in[5];
    const float* kb2 = (const float*)d_in[6];
    const float* qw1 = (const float*)d_in[7];
    const float* qb1 = (const float*)d_in[8];
    const float* qw2 = (const float*)d_in[9];
    const float* qb2 = (const float*)d_in[10];
    const float* qw3 = (const float*)d_in[11];
    const float* qb3 = (const float*)d_in[12];
    float* out = (float*)d_out;

    float *p_k1, *p_k, *p_q1, *p_q;
    cudaGetSymbolAddress((void**)&p_k1, g_k1);
    cudaGetSymbolAddress((void**)&p_k,  g_k);
    cudaGetSymbolAddress((void**)&p_q1, g_q1);
    cudaGetSymbolAddress((void**)&p_q,  g_q);

    const int SM_B = 2 * 16 * 68 * 4 + 2 * 80 * 17 * 8 + 80 * HROW * 4 + 6400 * 4; // 77824
    const int SM_C = (80 * KROW + 80 * 32 + KROW + 32) * 4;                        // 82944

    cudaFuncSetAttribute(convA, cudaFuncAttributeMaxDynamicSharedMemorySize, SM_A);
    cudaFuncSetAttribute(convB, cudaFuncAttributeMaxDynamicSharedMemorySize, SM_B);
    cudaFuncSetAttribute(attn_kernel, cudaFuncAttributeMaxDynamicSharedMemorySize, SM_C);

    // one-time-per-call weight pair packing
    prep_w<<<(KW1P_N + QW1P_N + 255) / 256, 256>>>(kw1, qw1);

    convA<<<KEY_A_BLKS + QRY_A_BLKS, 64, SM_A>>>(
        keys, kb1, p_k1, queries, qb1, p_q1);
    convB<<<KEY_B_BLKS + QRY_B_BLKS, 128, SM_B>>>(
        p_k1, kw2, kb2, p_k, p_q1, qw2, qb2, qw3, qb3, p_q);
    attn_kernel<<<dim3(T1 / 32, B), 256, SM_C>>>(p_q, p_k, prior, out);
}

// round 7
// speedup vs baseline: 1.3420x; 1.0192x over previous
#include <cuda_runtime.h>
#include <math.h>

// ---------------- problem constants ----------------
#define B    16
#define T1   800
#define T2   200
#define CATT 80

typedef unsigned long long u64;

__device__ __forceinline__ u64 pk2(float lo, float hi) {
    u64 r; asm("mov.b64 %0,{%1,%2};" : "=l"(r) : "f"(lo), "f"(hi)); return r;
}
__device__ __forceinline__ void upk2(u64 v, float& lo, float& hi) {
    asm("mov.b64 {%0,%1},%2;" : "=f"(lo), "=f"(hi) : "l"(v));
}
__device__ __forceinline__ void ffma2(u64& d, u64 a, u64 b) {
    asm("fma.rn.f32x2 %0,%1,%2,%0;" : "+l"(d) : "l"(a), "l"(b));
}
__device__ __forceinline__ void cpa16(unsigned dst, const void* src) {
    asm volatile("cp.async.cg.shared.global [%0], [%1], 16;\n"
                 :: "r"(dst), "l"(src) : "memory");
}
#define CPA_COMMIT() asm volatile("cp.async.commit_group;\n" ::: "memory")
#define CPA_WAIT0()  asm volatile("cp.async.wait_group 0;\n" ::: "memory")

// ---------------- scratch ----------------
__device__ float g_k1[B * 512 * T2];   // key conv1 out
__device__ float g_k [B * CATT * T2];  // key encoder out
__device__ float g_q1[B * 160 * T1];   // query conv1 out
__device__ float g_q [B * CATT * T1];  // query encoder out

// pair-packed weights: [chunk c][co-pair][ck 0..7][tap 0..2] u64 = (w[2p], w[2p+1])
#define KW1P_N (32 * 256 * 24)   // 196608
#define QW1P_N (10 * 80 * 24)    // 19200
__device__ alignas(16) u64 g_kw1p[KW1P_N];
__device__ alignas(16) u64 g_qw1p[QW1P_N];

// ============================================================
// one-time weight pair-packing
// ============================================================
__global__ void prep_w(const float* __restrict__ kw1, const float* __restrict__ qw1)
{
    int idx = blockIdx.x * 256 + threadIdx.x;
    if (idx < KW1P_N) {
        int k  = idx % 3;
        int ck = (idx / 3) & 7;
        int p  = (idx / 24) & 255;
        int c  = idx / (24 * 256);
        int cin = c * 8 + ck;
        g_kw1p[idx] = pk2(kw1[(size_t)(2 * p) * 768 + cin * 3 + k],
                          kw1[(size_t)(2 * p + 1) * 768 + cin * 3 + k]);
    } else if (idx < KW1P_N + QW1P_N) {
        int j  = idx - KW1P_N;
        int k  = j % 3;
        int ck = (j / 3) & 7;
        int p  = (j / 24) % 80;
        int c  = j / (24 * 80);
        int cin = c * 8 + ck;
        g_qw1p[j] = pk2(qw1[(size_t)(2 * p) * 240 + cin * 3 + k],
                        qw1[(size_t)(2 * p + 1) * 240 + cin * 3 + k]);
    }
}

// ============================================================
// k=3 conv body, pad=1. 64 threads, micro 8co(4 pairs) x 8t(2 groups of 4).
// X stored dup (x,x) u64 in smem; W pair-packed via cp.async.
// ============================================================
template<int TCO, int TT, int CIN, int RELU, int NPG>
__device__ __forceinline__ void conv3_pair(
    const float* __restrict__ xb,   // x + b*CIN*T
    const u64*  __restrict__ wp,    // pair-packed weights
    const float* __restrict__ bias,
    float* __restrict__ yb,         // y + b*COUT*T
    int T, int co0, int t0, int tid, char* sm)
{
    constexpr int CK    = 8;
    constexpr int NC    = CIN / CK;
    constexpr int TTHR  = TT / 8;
    constexpr int COTHR = TCO / 8;
    static_assert(COTHR * TTHR == 64, "layout");
    constexpr int XCOLS = TT + 2;             // even -> rows 16B aligned
    constexpr int XTOT  = CK * XCOLS;
    constexpr int XLD   = (XTOT + 63) / 64;
    constexpr int NP    = TCO / 2;            // pairs per tile
    constexpr int WOPS  = NP * 12;            // 16B cp.async per chunk
    constexpr int WLD   = WOPS / 64;
    static_assert(WOPS % 64 == 0, "wops");
    constexpr int WPAD  = 26;                 // u64 per pair row (24 + pad)
    constexpr int H     = TT / 2;

    u64* Xd = (u64*)sm;                       // 2 * CK * XCOLS
    u64* Ws = Xd + 2 * CK * XCOLS;            // 2 * NP * WPAD

    const int ci = tid / TTHR;                // 0..COTHR-1
    const int tj = tid % TTHR;

    u64 acc[4][8];
    #pragma unroll
    for (int i = 0; i < 4; i++)
        #pragma unroll
        for (int j = 0; j < 8; j++) acc[i][j] = 0ull;

    float xr[XLD];

    auto ldgX = [&](int c) {
        #pragma unroll
        for (int i = 0; i < XLD; i++) {
            int e = tid + i * 64;
            float v = 0.f;
            if (e < XTOT) {
                int r = e / XCOLS, col = e % XCOLS;
                int t = t0 + col - 1;
                if (t >= 0 && t < T) v = xb[(size_t)(c * CK + r) * T + t];
            }
            xr[i] = v;
        }
    };
    auto stsX = [&](int buf) {
        u64* Xb = Xd + buf * CK * XCOLS;
        #pragma unroll
        for (int i = 0; i < XLD; i++) {
            int e = tid + i * 64;
            if (e < XTOT) Xb[e] = pk2(xr[i], xr[i]);
        }
    };
    auto cpaW = [&](int c, int buf) {
        const char* slab = (const char*)(wp + ((size_t)c * NPG + (co0 >> 1)) * 24);
        unsigned wbs = (unsigned)__cvta_generic_to_shared(Ws + buf * NP * WPAD);
        #pragma unroll
        for (int i = 0; i < WLD; i++) {
            int e = tid + i * 64;
            int p = e / 12, o = e % 12;
            cpa16(wbs + p * (WPAD * 8) + o * 16, slab + p * 192 + o * 16);
        }
        CPA_COMMIT();
    };

    cpaW(0, 0);
    ldgX(0);
    stsX(0);
    CPA_WAIT0();
    __syncthreads();

    for (int c = 0; c < NC; c++) {
        if (c + 1 < NC) {
            cpaW(c + 1, (c + 1) & 1);
            ldgX(c + 1);
        }
        {
            const u64* X = Xd + (c & 1) * CK * XCOLS;
            const u64* W = Ws + (c & 1) * NP * WPAD;
            #pragma unroll
            for (int ck = 0; ck < CK; ck++) {
                const u64* xrow = X + ck * XCOLS;
                ulonglong2 a0 = *(const ulonglong2*)(xrow + tj * 4);
                ulonglong2 a1 = *(const ulonglong2*)(xrow + tj * 4 + 2);
                ulonglong2 a2 = *(const ulonglong2*)(xrow + tj * 4 + 4);
                ulonglong2 b0 = *(const ulonglong2*)(xrow + tj * 4 + H);
                ulonglong2 b1 = *(const ulonglong2*)(xrow + tj * 4 + H + 2);
                ulonglong2 b2 = *(const ulonglong2*)(xrow + tj * 4 + H + 4);
                u64 d[6] = {a0.x, a0.y, a1.x, a1.y, a2.x, a2.y};
                u64 e2[6] = {b0.x, b0.y, b1.x, b1.y, b2.x, b2.y};
                #pragma unroll
                for (int i = 0; i < 4; i++) {
                    const u64* wr = W + (size_t)(ci * 4 + i) * WPAD + ck * 3;
                    u64 w0 = wr[0], w1 = wr[1], w2 = wr[2];
                    #pragma unroll
                    for (int j = 0; j < 4; j++) {
                        ffma2(acc[i][j], d[j],      w0);
                        ffma2(acc[i][j], d[j + 1],  w1);
                        ffma2(acc[i][j], d[j + 2],  w2);
                        ffma2(acc[i][4 + j], e2[j],     w0);
                        ffma2(acc[i][4 + j], e2[j + 1], w1);
                        ffma2(acc[i][4 + j], e2[j + 2], w2);
                    }
                }
            }
        }
        if (c + 1 < NC) {
            stsX((c + 1) & 1);
            CPA_WAIT0();
            __syncthreads();
        }
    }

    #pragma unroll
    for (int i = 0; i < 4; i++) {
        int coA = co0 + (ci * 4 + i) * 2;
        int coB = coA + 1;
        float bA = bias[coA], bB = bias[coB];
        #pragma unroll
        for (int g = 0; g < 2; g++) {
            int t = t0 + tj * 4 + g * H;
            if (t < T) {
                float a0, c0, a1, c1, a2, c2, a3, c3;
                upk2(acc[i][g * 4 + 0], a0, c0);
                upk2(acc[i][g * 4 + 1], a1, c1);
                upk2(acc[i][g * 4 + 2], a2, c2);
                upk2(acc[i][g * 4 + 3], a3, c3);
                float4 fA = make_float4(a0 + bA, a1 + bA, a2 + bA, a3 + bA);
                float4 fB = make_float4(c0 + bB, c1 + bB, c2 + bB, c3 + bB);
                if (RELU) {
                    fA.x = fmaxf(fA.x, 0.f); fA.y = fmaxf(fA.y, 0.f);
                    fA.z = fmaxf(fA.z, 0.f); fA.w = fmaxf(fA.w, 0.f);
                    fB.x = fmaxf(fB.x, 0.f); fB.y = fmaxf(fB.y, 0.f);
                    fB.z = fmaxf(fB.z, 0.f); fB.w = fmaxf(fB.w, 0.f);
                }
                *(float4*)(yb + (size_t)coA * T + t) = fA;
                *(float4*)(yb + (size_t)coB * T + t) = fB;
            }
        }
    }
}

// ---- kernel A: key conv1 (256->512 k3) + query conv1 (80->160 k3) ----
#define KEY_A_BLKS (4 * 7 * B)     // 448
#define QRY_A_BLKS (5 * 7 * B)     // 560
__global__ __launch_bounds__(64, 6) void convA(
    const float* __restrict__ keys, const float* __restrict__ kb1,
    float* __restrict__ k1out,
    const float* __restrict__ qsrc, const float* __restrict__ qb1,
    float* __restrict__ q1out)
{
    extern __shared__ char sm[];
    const int bid = blockIdx.x, tid = threadIdx.x;
    if (bid < KEY_A_BLKS) {
        int b = bid / 28, r = bid % 28;
        int co0 = (r / 7) * 128, t0 = (r % 7) * 32;
        conv3_pair<128, 32, 256, 1, 256>(keys + (size_t)b * 256 * T2, g_kw1p, kb1,
                                         k1out + (size_t)b * 512 * T2, T2, co0, t0, tid, sm);
    } else {
        int qb = bid - KEY_A_BLKS;
        int b = qb / 35, r = qb % 35;
        int co0 = (r / 7) * 32, t0 = (r % 7) * 128;
        conv3_pair<32, 128, 80, 1, 80>(qsrc + (size_t)b * 80 * T1, g_qw1p, qb1,
                                       q1out + (size_t)b * 160 * T1, T1, co0, t0, tid, sm);
    }
}
#define SM_A 30976

// ============================================================
// k=1 accumulate body: 80 couts x 64 t tile, micro 5co x 8t, CK=16.
// ============================================================
template<int CIN>
__device__ __forceinline__ void k1_accum(
    const float* __restrict__ xb, int T, int t0,
    const float* __restrict__ w,   // (80, CIN)
    float* Xs, float2* Ws, u64 (&acc)[5][4], int tid)
{
    constexpr int CK = 16, XROW = 68, WROW = 17;
    constexpr int NC = CIN / CK;
    constexpr int WLD = 80 * CK / 128;   // 10
    constexpr int XLD = CK * 64 / 128;   // 8
    const int ci = tid >> 3, tj = tid & 7;

    float wr_[WLD], xr_[XLD];
    #pragma unroll
    for (int i = 0; i < WLD; i++) {
        int e = tid + i * 128; int r = e / CK, cc = e % CK;
        wr_[i] = w[(size_t)r * CIN + cc];
    }
    #pragma unroll
    for (int i = 0; i < XLD; i++) {
        int e = tid + i * 128; int r = e / 64, cc = e % 64;
        int t = t0 + cc;
        xr_[i] = (t < T) ? xb[(size_t)r * T + t] : 0.f;
    }
    #pragma unroll
    for (int i = 0; i < WLD; i++) {
        int e = tid + i * 128; int r = e / CK, cc = e % CK;
        Ws[r * WROW + cc] = make_float2(wr_[i], wr_[i]);
    }
    #pragma unroll
    for (int i = 0; i < XLD; i++) {
        int e = tid + i * 128; int r = e / 64, cc = e % 64;
        Xs[r * XROW + cc] = xr_[i];
    }
    __syncthreads();

    for (int c = 0; c < NC; c++) {
        if (c + 1 < NC) {
            const int c0 = (c + 1) * CK;
            #pragma unroll
            for (int i = 0; i < WLD; i++) {
                int e = tid + i * 128; int r = e / CK, cc = e % CK;
                wr_[i] = w[(size_t)r * CIN + c0 + cc];
            }
            #pragma unroll
            for (int i = 0; i < XLD; i++) {
                int e = tid + i * 128; int r = e / 64, cc = e % 64;
                int t = t0 + cc;
                xr_[i] = (t < T) ? xb[(size_t)(c0 + r) * T + t] : 0.f;
            }
        }
        const float*  X = Xs + (c & 1) * CK * XROW;
        const float2* W = Ws + (c & 1) * 80 * WROW;
        #pragma unroll
        for (int ck = 0; ck < CK; ck++) {
            const ulonglong2* xp = (const ulonglong2*)(X + ck * XROW + tj * 8);
            ulonglong2 A = xp[0], Bv = xp[1];
            #pragma unroll
            for (int i = 0; i < 5; i++) {
                u64 wv = *(const u64*)(W + (size_t)(ci * 5 + i) * WROW + ck);
                ffma2(acc[i][0], A.x,  wv); ffma2(acc[i][1], A.y,  wv);
                ffma2(acc[i][2], Bv.x, wv); ffma2(acc[i][3], Bv.y, wv);
            }
        }
        if (c + 1 < NC) {
            __syncthreads();
            float*  Xd = Xs + ((c + 1) & 1) * CK * XROW;
            float2* Wd = Ws + ((c + 1) & 1) * 80 * WROW;
            #pragma unroll
            for (int i = 0; i < WLD; i++) {
                int e = tid + i * 128; int r = e / CK, cc = e % CK;
                Wd[r * WROW + cc] = make_float2(wr_[i], wr_[i]);
            }
            #pragma unroll
            for (int i = 0; i < XLD; i++) {
                int e = tid + i * 128; int r = e / 64, cc = e % 64;
                Xd[r * XROW + cc] = xr_[i];
            }
            __syncthreads();
        }
    }
}

// ---- kernel B: key conv2 (512->80 k1) + fused query conv2+3 ----
#define KEY_B_BLKS (4 * B)     // 64
#define QRY_B_BLKS (13 * B)    // 208
#define HROW 68
__global__ __launch_bounds__(128, 3) void convB(
    const float* __restrict__ k1in, const float* __restrict__ kw2,
    const float* __restrict__ kb2, float* __restrict__ kout,
    const float* __restrict__ q1in,
    const float* __restrict__ qw2, const float* __restrict__ qb2,
    const float* __restrict__ qw3, const float* __restrict__ qb3,
    float* __restrict__ qout)
{
    extern __shared__ char sm[];
    float*  Xs  = (float*)sm;
    float2* Ws  = (float2*)(sm + 2 * 16 * 68 * 4);
    float*  Hs  = (float*)((char*)Ws + 2 * 80 * 17 * 8);
    float*  W3s = Hs + 80 * HROW;

    const int bid = blockIdx.x, tid = threadIdx.x;
    const int ci = tid >> 3, tj = tid & 7;

    u64 acc[5][4];
    #pragma unroll
    for (int i = 0; i < 5; i++)
        #pragma unroll
        for (int p = 0; p < 4; p++) acc[i][p] = 0ull;

    if (bid < KEY_B_BLKS) {
        int b = bid / 4, t0 = (bid % 4) * 64;
        k1_accum<512>(k1in + (size_t)b * 512 * T2, T2, t0, kw2, Xs, Ws, acc, tid);
        float* yb = kout + (size_t)b * 80 * T2;
        #pragma unroll
        for (int i = 0; i < 5; i++) {
            int co = ci * 5 + i;
            float bb = kb2[co];
            float v[8];
            #pragma unroll
            for (int p = 0; p < 4; p++) upk2(acc[i][p], v[2 * p], v[2 * p + 1]);
            #pragma unroll
            for (int j = 0; j < 8; j++) {
                int t = t0 + tj * 8 + j;
                if (t < T2) yb[(size_t)co * T2 + t] = v[j] + bb;
            }
        }
    } else {
        int qb = bid - KEY_B_BLKS;
        int b = qb / 13, t0 = (qb % 13) * 64;
        for (int e = tid; e < 6400; e += 128) W3s[e] = qw3[e];
        k1_accum<160>(q1in + (size_t)b * 160 * T1, T1, t0, qw2, Xs, Ws, acc, tid);
        #pragma unroll
        for (int i = 0; i < 5; i++) {
            int co = ci * 5 + i;
            float bb = qb2[co];
            float v[8];
            #pragma unroll
            for (int p = 0; p < 4; p++) upk2(acc[i][p], v[2 * p], v[2 * p + 1]);
            float4 h0, h1;
            h0.x = fmaxf(v[0] + bb, 0.f); h0.y = fmaxf(v[1] + bb, 0.f);
            h0.z = fmaxf(v[2] + bb, 0.f); h0.w = fmaxf(v[3] + bb, 0.f);
            h1.x = fmaxf(v[4] + bb, 0.f); h1.y = fmaxf(v[5] + bb, 0.f);
            h1.z = fmaxf(v[6] + bb, 0.f); h1.w = fmaxf(v[7] + bb, 0.f);
            *(float4*)(Hs + (size_t)co * HROW + tj * 8) = h0;
            *(float4*)(Hs + (size_t)co * HROW + tj * 8 + 4) = h1;
        }
        __syncthreads();

        u64 acc2[5][4];
        #pragma unroll
        for (int i = 0; i < 5; i++)
            #pragma unroll
            for (int p = 0; p < 4; p++) acc2[i][p] = 0ull;

        #pragma unroll 4
        for (int ck = 0; ck < 80; ck++) {
            const ulonglong2* xp = (const ulonglong2*)(Hs + (size_t)ck * HROW + tj * 8);
            ulonglong2 A = xp[0], Bv = xp[1];
            #pragma unroll
            for (int i = 0; i < 5; i++) {
                float wv = W3s[(size_t)(ci * 5 + i) * 80 + ck];
                u64 wpk = pk2(wv, wv);
                ffma2(acc2[i][0], A.x,  wpk); ffma2(acc2[i][1], A.y,  wpk);
                ffma2(acc2[i][2], Bv.x, wpk); ffma2(acc2[i][3], Bv.y, wpk);
            }
        }

        float* yb = qout + (size_t)b * 80 * T1;
        #pragma unroll
        for (int i = 0; i < 5; i++) {
            int co = ci * 5 + i;
            float bb = qb3[co];
            float v[8];
            #pragma unroll
            for (int p = 0; p < 4; p++) upk2(acc2[i][p], v[2 * p], v[2 * p + 1]);
            #pragma unroll
            for (int j = 0; j < 8; j++) {
                int t = t0 + tj * 8 + j;
                if (t < T1) yb[(size_t)co * T1 + t] = v[j] + bb;
            }
        }
    }
}

// ============================================================
// Attention v2: t2-pair FFMA2 GEMM + log_softmax + log prior.
// Block = 256 threads, 64 t1 rows. Warp w owns rows w*8..w*8+7.
// Lane covers t2-pairs p = lane + 32*jp (jp=0..3; pairs 0..99 valid).
// smem: ks (80x200 f32, natural pairs), qd (80x64 u64 dup), k2s, q2s.
// ============================================================
#define NPAIR 100
__global__ __launch_bounds__(256, 2) void attn_kernel(
    const float* __restrict__ q, const float* __restrict__ k,
    const float* __restrict__ prior, float* __restrict__ out)
{
    extern __shared__ char smc[];
    float* ks  = (float*)smc;                    // 80*200
    u64*   qd  = (u64*)(smc + 80 * T2 * 4);      // 80*64
    float* k2s = (float*)(qd + 80 * 64);         // 200
    float* q2s = k2s + T2;                       // 64

    const int b   = blockIdx.y;
    const int t10 = blockIdx.x * 64;
    const int tid = threadIdx.x;

    const float* kb = k + (size_t)b * CATT * T2;
    const float* qb = q + (size_t)b * CATT * T1;

    // load K (contiguous float4 copy)
    for (int i = tid; i < 80 * T2 / 4; i += 256)
        ((float4*)ks)[i] = ((const float4*)kb)[i];
    // load Q duplicated
    for (int i = tid; i < 80 * 64; i += 256) {
        int c = i >> 6, r = i & 63;
        int t = t10 + r;
        float v = (t < T1) ? qb[(size_t)c * T1 + t] : 0.f;
        qd[i] = pk2(v, v);
    }
    __syncthreads();

    // norms
    if (tid < T2) {
        float s = 0.f;
        #pragma unroll 8
        for (int c = 0; c < 80; c++) { float v = ks[c * T2 + tid]; s += v * v; }
        k2s[tid] = s;
    }
    if (tid >= 192) {
        int r = tid - 192;
        float s = 0.f;
        #pragma unroll 8
        for (int c = 0; c < 80; c++) { float lo, hi; upk2(qd[c * 64 + r], lo, hi); s += lo * lo; }
        q2s[r] = s;
    }
    __syncthreads();

    const int warp = tid >> 5, lane = tid & 31;
    const int o0 = lane, o1 = lane + 32, o2 = lane + 64;
    const int o3 = (lane < 4) ? lane + 96 : 0;   // clamped; masked later
    const bool v3 = (lane < 4);

    u64 dot[8][4];
    #pragma unroll
    for (int i = 0; i < 8; i++)
        #pragma unroll
        for (int j = 0; j < 4; j++) dot[i][j] = 0ull;

    const u64* kp = (const u64*)ks;
    #pragma unroll 2
    for (int c = 0; c < 80; c++) {
        u64 k0 = kp[c * NPAIR + o0];
        u64 k1 = kp[c * NPAIR + o1];
        u64 k2 = kp[c * NPAIR + o2];
        u64 k3 = kp[c * NPAIR + o3];
        const u64* qrow = qd + c * 64 + warp * 8;
        ulonglong2 qa = *(const ulonglong2*)qrow;
        ulonglong2 qbv = *(const ulonglong2*)(qrow + 2);
        ulonglong2 qc = *(const ulonglong2*)(qrow + 4);
        ulonglong2 qdv = *(const ulonglong2*)(qrow + 6);
        u64 qv[8] = {qa.x, qa.y, qbv.x, qbv.y, qc.x, qc.y, qdv.x, qdv.y};
        #pragma unroll
        for (int i = 0; i < 8; i++) {
            ffma2(dot[i][0], qv[i], k0);
            ffma2(dot[i][1], qv[i], k1);
            ffma2(dot[i][2], qv[i], k2);
            ffma2(dot[i][3], qv[i], k3);
        }
    }

    const u64* k2p = (const u64*)k2s;
    u64 kn[4] = {k2p[o0], k2p[o1], k2p[o2], k2p[o3]};

    #pragma unroll
    for (int i = 0; i < 8; i++) {
        int r  = warp * 8 + i;
        int t1 = t10 + r;
        if (t1 >= T1) break;
        float q2 = q2s[r];
        float xe[4], xo[4];
        #pragma unroll
        for (int j = 0; j < 4; j++) {
            float de, dofl, ke, ko;
            upk2(dot[i][j], de, dofl);
            upk2(kn[j], ke, ko);
            xe[j] = -0.0005f * (q2 + ke - 2.f * de);
            xo[j] = -0.0005f * (q2 + ko - 2.f * dofl);
        }
        // row max
        float m = fmaxf(xe[0], xo[0]);
        m = fmaxf(m, fmaxf(xe[1], xo[1]));
        m = fmaxf(m, fmaxf(xe[2], xo[2]));
        if (v3) m = fmaxf(m, fmaxf(xe[3], xo[3]));
        #pragma unroll
        for (int off = 16; off; off >>= 1)
            m = fmaxf(m, __shfl_xor_sync(0xFFFFFFFFu, m, off));
        // sum exp
        float s = __expf(xe[0] - m) + __expf(xo[0] - m)
                + __expf(xe[1] - m) + __expf(xo[1] - m)
                + __expf(xe[2] - m) + __expf(xo[2] - m);
        if (v3) s += __expf(xe[3] - m) + __expf(xo[3] - m);
        #pragma unroll
        for (int off = 16; off; off >>= 1)
            s += __shfl_xor_sync(0xFFFFFFFFu, s, off);
        float lse = m + __logf(s);

        const float2* pr = (const float2*)(prior + ((size_t)b * T1 + t1) * T2);
        float2* ob = (float2*)(out + ((size_t)b * T1 + t1) * T2);
        #pragma unroll
        for (int j = 0; j < 4; j++) {
            if (j == 3 && !v3) break;
            int p = lane + 32 * j;
            float2 pv = pr[p];
            float2 ov;
            ov.x = xe[j] - lse + __logf(pv.x + 1e-8f);
            ov.y = xo[j] - lse + __logf(pv.y + 1e-8f);
            ob[p] = ov;
        }
    }
}
#define SM_ATT (80 * T2 * 4 + 80 * 64 * 8 + T2 * 4 + 64 * 4)   // 106016

// ============================================================
// launch
// ============================================================
extern "C" void kernel_launch(void* const* d_in, const int* in_sizes, int n_in,
                              void* d_out, int out_size)
{
    const float* queries = (const float*)d_in[0];
    const float* keys    = (const float*)d_in[1];
    const float* prior   = (const float*)d_in[2];
    const float* kw1 = (const float*)d_in[3];
    const float* kb1 = (const float*)d_in[4];
    const float* kw2 = (const float*)d_in[5];
    const float* kb2 = (const float*)d_in[6];
    const float* qw1 = (const float*)d_in[7];
    const float* qb1 = (const float*)d_in[8];
    const float* qw2 = (const float*)d_in[9];
    const float* qb2 = (const float*)d_in[10];
    const float* qw3 = (const float*)d_in[11];
    const float* qb3 = (const float*)d_in[12];
    float* out = (float*)d_out;

    float *p_k1, *p_k, *p_q1, *p_q;
    cudaGetSymbolAddress((void**)&p_k1, g_k1);
    cudaGetSymbolAddress((void**)&p_k,  g_k);
    cudaGetSymbolAddress((void**)&p_q1, g_q1);
    cudaGetSymbolAddress((void**)&p_q,  g_q);

    const int SM_B = 2 * 16 * 68 * 4 + 2 * 80 * 17 * 8 + 80 * HROW * 4 + 6400 * 4; // 77824

    cudaFuncSetAttribute(convA, cudaFuncAttributeMaxDynamicSharedMemorySize, SM_A);
    cudaFuncSetAttribute(convB, cudaFuncAttributeMaxDynamicSharedMemorySize, SM_B);
    cudaFuncSetAttribute(attn_kernel, cudaFuncAttributeMaxDynamicSharedMemorySize, SM_ATT);

    prep_w<<<(KW1P_N + QW1P_N + 255) / 256, 256>>>(kw1, qw1);

    convA<<<KEY_A_BLKS + QRY_A_BLKS, 64, SM_A>>>(
        keys, kb1, p_k1, queries, qb1, p_q1);
    convB<<<KEY_B_BLKS + QRY_B_BLKS, 128, SM_B>>>(
        p_k1, kw2, kb2, p_k, p_q1, qw2, qb2, qw3, qb3, p_q);
    attn_kernel<<<dim3((T1 + 63) / 64, B), 256, SM_ATT>>>(p_q, p_k, prior, out);
}

// round 9
// speedup vs baseline: 1.3867x; 1.0333x over previous
#include <cuda_runtime.h>
#include <math.h>

// ---------------- problem constants ----------------
#define B    16
#define T1   800
#define T2   200
#define CATT 80

typedef unsigned long long u64;

__device__ __forceinline__ u64 pk2(float lo, float hi) {
    u64 r; asm("mov.b64 %0,{%1,%2};" : "=l"(r) : "f"(lo), "f"(hi)); return r;
}
__device__ __forceinline__ void upk2(u64 v, float& lo, float& hi) {
    asm("mov.b64 {%0,%1},%2;" : "=f"(lo), "=f"(hi) : "l"(v));
}
__device__ __forceinline__ void ffma2(u64& d, u64 a, u64 b) {
    asm("fma.rn.f32x2 %0,%1,%2,%0;" : "+l"(d) : "l"(a), "l"(b));
}
__device__ __forceinline__ void cpa16(unsigned dst, const void* src) {
    asm volatile("cp.async.cg.shared.global [%0], [%1], 16;\n"
                 :: "r"(dst), "l"(src) : "memory");
}
#define CPA_COMMIT() asm volatile("cp.async.commit_group;\n" ::: "memory")
#define CPA_WAIT0()  asm volatile("cp.async.wait_group 0;\n" ::: "memory")

// ---------------- scratch ----------------
__device__ float g_k1[B * 512 * T2];   // key conv1 out
__device__ float g_k [B * CATT * T2];  // key encoder out
__device__ float g_q1[B * 160 * T1];   // query conv1 out
__device__ float g_q [B * CATT * T1];  // query encoder out

// pair-packed weights: [chunk c][co-pair][ck 0..7][tap 0..2] u64 = (w[2p], w[2p+1])
#define KW1P_N (32 * 256 * 24)   // 196608
#define QW1P_N (10 * 80 * 24)    // 19200
__device__ alignas(16) u64 g_kw1p[KW1P_N];
__device__ alignas(16) u64 g_qw1p[QW1P_N];

// ============================================================
// one-time weight pair-packing
// ============================================================
__global__ void prep_w(const float* __restrict__ kw1, const float* __restrict__ qw1)
{
    int idx = blockIdx.x * 256 + threadIdx.x;
    if (idx < KW1P_N) {
        int k  = idx % 3;
        int ck = (idx / 3) & 7;
        int p  = (idx / 24) & 255;
        int c  = idx / (24 * 256);
        int cin = c * 8 + ck;
        g_kw1p[idx] = pk2(kw1[(size_t)(2 * p) * 768 + cin * 3 + k],
                          kw1[(size_t)(2 * p + 1) * 768 + cin * 3 + k]);
    } else if (idx < KW1P_N + QW1P_N) {
        int j  = idx - KW1P_N;
        int k  = j % 3;
        int ck = (j / 3) & 7;
        int p  = (j / 24) % 80;
        int c  = j / (24 * 80);
        int cin = c * 8 + ck;
        g_qw1p[j] = pk2(qw1[(size_t)(2 * p) * 240 + cin * 3 + k],
                        qw1[(size_t)(2 * p + 1) * 240 + cin * 3 + k]);
    }
}

// ============================================================
// k=3 conv body, pad=1. 64 threads, micro 8co(4 pairs) x 8t(2 groups of 4).
// ============================================================
template<int TCO, int TT, int CIN, int RELU, int NPG>
__device__ __forceinline__ void conv3_pair(
    const float* __restrict__ xb,
    const u64*  __restrict__ wp,
    const float* __restrict__ bias,
    float* __restrict__ yb,
    int T, int co0, int t0, int tid, char* sm)
{
    constexpr int CK    = 8;
    constexpr int NC    = CIN / CK;
    constexpr int TTHR  = TT / 8;
    constexpr int COTHR = TCO / 8;
    static_assert(COTHR * TTHR == 64, "layout");
    constexpr int XCOLS = TT + 2;
    constexpr int XTOT  = CK * XCOLS;
    constexpr int XLD   = (XTOT + 63) / 64;
    constexpr int NP    = TCO / 2;
    constexpr int WOPS  = NP * 12;
    constexpr int WLD   = WOPS / 64;
    static_assert(WOPS % 64 == 0, "wops");
    constexpr int WPAD  = 26;
    constexpr int H     = TT / 2;

    u64* Xd = (u64*)sm;
    u64* Ws = Xd + 2 * CK * XCOLS;

    const int ci = tid / TTHR;
    const int tj = tid % TTHR;

    u64 acc[4][8];
    #pragma unroll
    for (int i = 0; i < 4; i++)
        #pragma unroll
        for (int j = 0; j < 8; j++) acc[i][j] = 0ull;

    float xr[XLD];

    auto ldgX = [&](int c) {
        #pragma unroll
        for (int i = 0; i < XLD; i++) {
            int e = tid + i * 64;
            float v = 0.f;
            if (e < XTOT) {
                int r = e / XCOLS, col = e % XCOLS;
                int t = t0 + col - 1;
                if (t >= 0 && t < T) v = xb[(size_t)(c * CK + r) * T + t];
            }
            xr[i] = v;
        }
    };
    auto stsX = [&](int buf) {
        u64* Xb = Xd + buf * CK * XCOLS;
        #pragma unroll
        for (int i = 0; i < XLD; i++) {
            int e = tid + i * 64;
            if (e < XTOT) Xb[e] = pk2(xr[i], xr[i]);
        }
    };
    auto cpaW = [&](int c, int buf) {
        const char* slab = (const char*)(wp + ((size_t)c * NPG + (co0 >> 1)) * 24);
        unsigned wbs = (unsigned)__cvta_generic_to_shared(Ws + buf * NP * WPAD);
        #pragma unroll
        for (int i = 0; i < WLD; i++) {
            int e = tid + i * 64;
            int p = e / 12, o = e % 12;
            cpa16(wbs + p * (WPAD * 8) + o * 16, slab + p * 192 + o * 16);
        }
        CPA_COMMIT();
    };

    cpaW(0, 0);
    ldgX(0);
    stsX(0);
    CPA_WAIT0();
    __syncthreads();

    for (int c = 0; c < NC; c++) {
        if (c + 1 < NC) {
            cpaW(c + 1, (c + 1) & 1);
            ldgX(c + 1);
        }
        {
            const u64* X = Xd + (c & 1) * CK * XCOLS;
            const u64* W = Ws + (c & 1) * NP * WPAD;
            #pragma unroll
            for (int ck = 0; ck < CK; ck++) {
                const u64* xrow = X + ck * XCOLS;
                ulonglong2 a0 = *(const ulonglong2*)(xrow + tj * 4);
                ulonglong2 a1 = *(const ulonglong2*)(xrow + tj * 4 + 2);
                ulonglong2 a2 = *(const ulonglong2*)(xrow + tj * 4 + 4);
                ulonglong2 b0 = *(const ulonglong2*)(xrow + tj * 4 + H);
                ulonglong2 b1 = *(const ulonglong2*)(xrow + tj * 4 + H + 2);
                ulonglong2 b2 = *(const ulonglong2*)(xrow + tj * 4 + H + 4);
                u64 d[6] = {a0.x, a0.y, a1.x, a1.y, a2.x, a2.y};
                u64 e2[6] = {b0.x, b0.y, b1.x, b1.y, b2.x, b2.y};
                #pragma unroll
                for (int i = 0; i < 4; i++) {
                    const u64* wr = W + (size_t)(ci * 4 + i) * WPAD + ck * 3;
                    u64 w0 = wr[0], w1 = wr[1], w2 = wr[2];
                    #pragma unroll
                    for (int j = 0; j < 4; j++) {
                        ffma2(acc[i][j], d[j],      w0);
                        ffma2(acc[i][j], d[j + 1],  w1);
                        ffma2(acc[i][j], d[j + 2],  w2);
                        ffma2(acc[i][4 + j], e2[j],     w0);
                        ffma2(acc[i][4 + j], e2[j + 1], w1);
                        ffma2(acc[i][4 + j], e2[j + 2], w2);
                    }
                }
            }
        }
        if (c + 1 < NC) {
            stsX((c + 1) & 1);
            CPA_WAIT0();
            __syncthreads();
        }
    }

    #pragma unroll
    for (int i = 0; i < 4; i++) {
        int coA = co0 + (ci * 4 + i) * 2;
        int coB = coA + 1;
        float bA = bias[coA], bB = bias[coB];
        #pragma unroll
        for (int g = 0; g < 2; g++) {
            int t = t0 + tj * 4 + g * H;
            if (t < T) {
                float a0, c0, a1, c1, a2, c2, a3, c3;
                upk2(acc[i][g * 4 + 0], a0, c0);
                upk2(acc[i][g * 4 + 1], a1, c1);
                upk2(acc[i][g * 4 + 2], a2, c2);
                upk2(acc[i][g * 4 + 3], a3, c3);
                float4 fA = make_float4(a0 + bA, a1 + bA, a2 + bA, a3 + bA);
                float4 fB = make_float4(c0 + bB, c1 + bB, c2 + bB, c3 + bB);
                if (RELU) {
                    fA.x = fmaxf(fA.x, 0.f); fA.y = fmaxf(fA.y, 0.f);
                    fA.z = fmaxf(fA.z, 0.f); fA.w = fmaxf(fA.w, 0.f);
                    fB.x = fmaxf(fB.x, 0.f); fB.y = fmaxf(fB.y, 0.f);
                    fB.z = fmaxf(fB.z, 0.f); fB.w = fmaxf(fB.w, 0.f);
                }
                *(float4*)(yb + (size_t)coA * T + t) = fA;
                *(float4*)(yb + (size_t)coB * T + t) = fB;
            }
        }
    }
}

// ---- kernel A ----
#define KEY_A_BLKS (4 * 7 * B)
#define QRY_A_BLKS (5 * 7 * B)
__global__ __launch_bounds__(64, 6) void convA(
    const float* __restrict__ keys, const float* __restrict__ kb1,
    float* __restrict__ k1out,
    const float* __restrict__ qsrc, const float* __restrict__ qb1,
    float* __restrict__ q1out)
{
    extern __shared__ char sm[];
    const int bid = blockIdx.x, tid = threadIdx.x;
    if (bid < KEY_A_BLKS) {
        int b = bid / 28, r = bid % 28;
        int co0 = (r / 7) * 128, t0 = (r % 7) * 32;
        conv3_pair<128, 32, 256, 1, 256>(keys + (size_t)b * 256 * T2, g_kw1p, kb1,
                                         k1out + (size_t)b * 512 * T2, T2, co0, t0, tid, sm);
    } else {
        int qb = bid - KEY_A_BLKS;
        int b = qb / 35, r = qb % 35;
        int co0 = (r / 7) * 32, t0 = (r % 7) * 128;
        conv3_pair<32, 128, 80, 1, 80>(qsrc + (size_t)b * 80 * T1, g_qw1p, qb1,
                                       q1out + (size_t)b * 160 * T1, T1, co0, t0, tid, sm);
    }
}
#define SM_A 30976

// ============================================================
// k=1 accumulate body
// ============================================================
template<int CIN>
__device__ __forceinline__ void k1_accum(
    const float* __restrict__ xb, int T, int t0,
    const float* __restrict__ w,
    float* Xs, float2* Ws, u64 (&acc)[5][4], int tid)
{
    constexpr int CK = 16, XROW = 68, WROW = 17;
    constexpr int NC = CIN / CK;
    constexpr int WLD = 80 * CK / 128;
    constexpr int XLD = CK * 64 / 128;
    const int ci = tid >> 3, tj = tid & 7;

    float wr_[WLD], xr_[XLD];
    #pragma unroll
    for (int i = 0; i < WLD; i++) {
        int e = tid + i * 128; int r = e / CK, cc = e % CK;
        wr_[i] = w[(size_t)r * CIN + cc];
    }
    #pragma unroll
    for (int i = 0; i < XLD; i++) {
        int e = tid + i * 128; int r = e / 64, cc = e % 64;
        int t = t0 + cc;
        xr_[i] = (t < T) ? xb[(size_t)r * T + t] : 0.f;
    }
    #pragma unroll
    for (int i = 0; i < WLD; i++) {
        int e = tid + i * 128; int r = e / CK, cc = e % CK;
        Ws[r * WROW + cc] = make_float2(wr_[i], wr_[i]);
    }
    #pragma unroll
    for (int i = 0; i < XLD; i++) {
        int e = tid + i * 128; int r = e / 64, cc = e % 64;
        Xs[r * XROW + cc] = xr_[i];
    }
    __syncthreads();

    for (int c = 0; c < NC; c++) {
        if (c + 1 < NC) {
            const int c0 = (c + 1) * CK;
            #pragma unroll
            for (int i = 0; i < WLD; i++) {
                int e = tid + i * 128; int r = e / CK, cc = e % CK;
                wr_[i] = w[(size_t)r * CIN + c0 + cc];
            }
            #pragma unroll
            for (int i = 0; i < XLD; i++) {
                int e = tid + i * 128; int r = e / 64, cc = e % 64;
                int t = t0 + cc;
                xr_[i] = (t < T) ? xb[(size_t)(c0 + r) * T + t] : 0.f;
            }
        }
        const float*  X = Xs + (c & 1) * CK * XROW;
        const float2* W = Ws + (c & 1) * 80 * WROW;
        #pragma unroll
        for (int ck = 0; ck < CK; ck++) {
            const ulonglong2* xp = (const ulonglong2*)(X + ck * XROW + tj * 8);
            ulonglong2 A = xp[0], Bv = xp[1];
            #pragma unroll
            for (int i = 0; i < 5; i++) {
                u64 wv = *(const u64*)(W + (size_t)(ci * 5 + i) * WROW + ck);
                ffma2(acc[i][0], A.x,  wv); ffma2(acc[i][1], A.y,  wv);
                ffma2(acc[i][2], Bv.x, wv); ffma2(acc[i][3], Bv.y, wv);
            }
        }
        if (c + 1 < NC) {
            __syncthreads();
            float*  Xd = Xs + ((c + 1) & 1) * CK * XROW;
            float2* Wd = Ws + ((c + 1) & 1) * 80 * WROW;
            #pragma unroll
            for (int i = 0; i < WLD; i++) {
                int e = tid + i * 128; int r = e / CK, cc = e % CK;
                Wd[r * WROW + cc] = make_float2(wr_[i], wr_[i]);
            }
            #pragma unroll
            for (int i = 0; i < XLD; i++) {
                int e = tid + i * 128; int r = e / 64, cc = e % 64;
                Xd[r * XROW + cc] = xr_[i];
            }
            __syncthreads();
        }
    }
}

// ---- kernel B ----
#define KEY_B_BLKS (4 * B)
#define QRY_B_BLKS (13 * B)
#define HROW 68
__global__ __launch_bounds__(128, 3) void convB(
    const float* __restrict__ k1in, const float* __restrict__ kw2,
    const float* __restrict__ kb2, float* __restrict__ kout,
    const float* __restrict__ q1in,
    const float* __restrict__ qw2, const float* __restrict__ qb2,
    const float* __restrict__ qw3, const float* __restrict__ qb3,
    float* __restrict__ qout)
{
    extern __shared__ char sm[];
    float*  Xs  = (float*)sm;
    float2* Ws  = (float2*)(sm + 2 * 16 * 68 * 4);
    float*  Hs  = (float*)((char*)Ws + 2 * 80 * 17 * 8);
    float*  W3s = Hs + 80 * HROW;

    const int bid = blockIdx.x, tid = threadIdx.x;
    const int ci = tid >> 3, tj = tid & 7;

    u64 acc[5][4];
    #pragma unroll
    for (int i = 0; i < 5; i++)
        #pragma unroll
        for (int p = 0; p < 4; p++) acc[i][p] = 0ull;

    if (bid < KEY_B_BLKS) {
        int b = bid / 4, t0 = (bid % 4) * 64;
        k1_accum<512>(k1in + (size_t)b * 512 * T2, T2, t0, kw2, Xs, Ws, acc, tid);
        float* yb = kout + (size_t)b * 80 * T2;
        #pragma unroll
        for (int i = 0; i < 5; i++) {
            int co = ci * 5 + i;
            float bb = kb2[co];
            float v[8];
            #pragma unroll
            for (int p = 0; p < 4; p++) upk2(acc[i][p], v[2 * p], v[2 * p + 1]);
            #pragma unroll
            for (int j = 0; j < 8; j++) {
                int t = t0 + tj * 8 + j;
                if (t < T2) yb[(size_t)co * T2 + t] = v[j] + bb;
            }
        }
    } else {
        int qb = bid - KEY_B_BLKS;
        int b = qb / 13, t0 = (qb % 13) * 64;
        for (int e = tid; e < 6400; e += 128) W3s[e] = qw3[e];
        k1_accum<160>(q1in + (size_t)b * 160 * T1, T1, t0, qw2, Xs, Ws, acc, tid);
        #pragma unroll
        for (int i = 0; i < 5; i++) {
            int co = ci * 5 + i;
            float bb = qb2[co];
            float v[8];
            #pragma unroll
            for (int p = 0; p < 4; p++) upk2(acc[i][p], v[2 * p], v[2 * p + 1]);
            float4 h0, h1;
            h0.x = fmaxf(v[0] + bb, 0.f); h0.y = fmaxf(v[1] + bb, 0.f);
            h0.z = fmaxf(v[2] + bb, 0.f); h0.w = fmaxf(v[3] + bb, 0.f);
            h1.x = fmaxf(v[4] + bb, 0.f); h1.y = fmaxf(v[5] + bb, 0.f);
            h1.z = fmaxf(v[6] + bb, 0.f); h1.w = fmaxf(v[7] + bb, 0.f);
            *(float4*)(Hs + (size_t)co * HROW + tj * 8) = h0;
            *(float4*)(Hs + (size_t)co * HROW + tj * 8 + 4) = h1;
        }
        __syncthreads();

        u64 acc2[5][4];
        #pragma unroll
        for (int i = 0; i < 5; i++)
            #pragma unroll
            for (int p = 0; p < 4; p++) acc2[i][p] = 0ull;

        #pragma unroll 4
        for (int ck = 0; ck < 80; ck++) {
            const ulonglong2* xp = (const ulonglong2*)(Hs + (size_t)ck * HROW + tj * 8);
            ulonglong2 A = xp[0], Bv = xp[1];
            #pragma unroll
            for (int i = 0; i < 5; i++) {
                float wv = W3s[(size_t)(ci * 5 + i) * 80 + ck];
                u64 wpk = pk2(wv, wv);
                ffma2(acc2[i][0], A.x,  wpk); ffma2(acc2[i][1], A.y,  wpk);
                ffma2(acc2[i][2], Bv.x, wpk); ffma2(acc2[i][3], Bv.y, wpk);
            }
        }

        float* yb = qout + (size_t)b * 80 * T1;
        #pragma unroll
        for (int i = 0; i < 5; i++) {
            int co = ci * 5 + i;
            float bb = qb3[co];
            float v[8];
            #pragma unroll
            for (int p = 0; p < 4; p++) upk2(acc2[i][p], v[2 * p], v[2 * p + 1]);
            #pragma unroll
            for (int j = 0; j < 8; j++) {
                int t = t0 + tj * 8 + j;
                if (t < T1) yb[(size_t)co * T1 + t] = v[j] + bb;
            }
        }
    }
}

// ============================================================
// Attention v3: single-wave grid (144 blocks), 384 threads, 96 rows/block.
// t2-pair FFMA2 GEMM; softmax without max-shift (logits in (-1,0]).
// ============================================================
#define NPAIR 100
#define ROWS_PER_BLK 96
__global__ __launch_bounds__(384, 1) void attn_kernel(
    const float* __restrict__ q, const float* __restrict__ k,
    const float* __restrict__ prior, float* __restrict__ out)
{
    extern __shared__ char smc[];
    float* ks  = (float*)smc;                          // 80*200
    u64*   qd  = (u64*)(smc + 80 * T2 * 4);            // 80*96
    float* k2s = (float*)(qd + 80 * ROWS_PER_BLK);     // 200
    float* q2s = k2s + T2;                             // 96

    const int b   = blockIdx.y;
    const int t10 = blockIdx.x * ROWS_PER_BLK;
    const int tid = threadIdx.x;

    const float* kb = k + (size_t)b * CATT * T2;
    const float* qb = q + (size_t)b * CATT * T1;

    // load K (contiguous float4 copy)
    for (int i = tid; i < 80 * T2 / 4; i += 384)
        ((float4*)ks)[i] = ((const float4*)kb)[i];
    // load Q duplicated
    for (int i = tid; i < 80 * ROWS_PER_BLK; i += 384) {
        int c = i / ROWS_PER_BLK, r = i % ROWS_PER_BLK;
        int t = t10 + r;
        float v = (t < T1) ? qb[(size_t)c * T1 + t] : 0.f;
        qd[i] = pk2(v, v);
    }
    __syncthreads();

    // norms
    if (tid < T2) {
        float s = 0.f;
        #pragma unroll 8
        for (int c = 0; c < 80; c++) { float v = ks[c * T2 + tid]; s += v * v; }
        k2s[tid] = s;
    }
    if (tid >= 384 - ROWS_PER_BLK) {
        int r = tid - (384 - ROWS_PER_BLK);
        float s = 0.f;
        #pragma unroll 8
        for (int c = 0; c < 80; c++) {
            float lo, hi; upk2(qd[c * ROWS_PER_BLK + r], lo, hi); s += lo * lo;
        }
        q2s[r] = s;
    }
    __syncthreads();

    const int warp = tid >> 5, lane = tid & 31;
    const int o0 = lane, o1 = lane + 32, o2 = lane + 64;
    const int o3 = (lane < 4) ? lane + 96 : 0;   // clamped; masked later
    const bool v3 = (lane < 4);

    u64 dot[8][4];
    #pragma unroll
    for (int i = 0; i < 8; i++)
        #pragma unroll
        for (int j = 0; j < 4; j++) dot[i][j] = 0ull;

    const u64* kp = (const u64*)ks;
    #pragma unroll 2
    for (int c = 0; c < 80; c++) {
        u64 k0 = kp[c * NPAIR + o0];
        u64 k1 = kp[c * NPAIR + o1];
        u64 k2 = kp[c * NPAIR + o2];
        u64 k3 = kp[c * NPAIR + o3];
        const u64* qrow = qd + c * ROWS_PER_BLK + warp * 8;
        ulonglong2 qa = *(const ulonglong2*)qrow;
        ulonglong2 qbv = *(const ulonglong2*)(qrow + 2);
        ulonglong2 qc = *(const ulonglong2*)(qrow + 4);
        ulonglong2 qdv = *(const ulonglong2*)(qrow + 6);
        u64 qv[8] = {qa.x, qa.y, qbv.x, qbv.y, qc.x, qc.y, qdv.x, qdv.y};
        #pragma unroll
        for (int i = 0; i < 8; i++) {
            ffma2(dot[i][0], qv[i], k0);
            ffma2(dot[i][1], qv[i], k1);
            ffma2(dot[i][2], qv[i], k2);
            ffma2(dot[i][3], qv[i], k3);
        }
    }

    const u64* k2p = (const u64*)k2s;
    u64 kn[4] = {k2p[o0], k2p[o1], k2p[o2], k2p[o3]};

    #pragma unroll
    for (int i = 0; i < 8; i++) {
        int r  = warp * 8 + i;
        int t1 = t10 + r;
        if (t1 >= T1) break;
        float q2 = q2s[r];

        // prefetch prior early (overlap LDG with reduction)
        const float2* pr = (const float2*)(prior + ((size_t)b * T1 + t1) * T2);
        float2 pv[4];
        pv[0] = pr[o0]; pv[1] = pr[o1]; pv[2] = pr[o2];
        if (v3) pv[3] = pr[o3];

        float xe[4], xo[4];
        #pragma unroll
        for (int j = 0; j < 4; j++) {
            float de, dofl, ke, ko;
            upk2(dot[i][j], de, dofl);
            upk2(kn[j], ke, ko);
            xe[j] = -0.0005f * (q2 + ke - 2.f * de);
            xo[j] = -0.0005f * (q2 + ko - 2.f * dofl);
        }
        // sum exp (no max shift: logits are O(-1..0), safe)
        float s = __expf(xe[0]) + __expf(xo[0])
                + __expf(xe[1]) + __expf(xo[1])
                + __expf(xe[2]) + __expf(xo[2]);
        if (v3) s += __expf(xe[3]) + __expf(xo[3]);
        #pragma unroll
        for (int off = 16; off; off >>= 1)
            s += __shfl_xor_sync(0xFFFFFFFFu, s, off);
        float lse = __logf(s);

        float2* ob = (float2*)(out + ((size_t)b * T1 + t1) * T2);
        #pragma unroll
        for (int j = 0; j < 4; j++) {
            if (j == 3 && !v3) break;
            int p = lane + 32 * j;
            float2 ov;
            ov.x = xe[j] - lse + __logf(pv[j].x + 1e-8f);
            ov.y = xo[j] - lse + __logf(pv[j].y + 1e-8f);
            ob[p] = ov;
        }
    }
}
#define SM_ATT (80 * T2 * 4 + 80 * ROWS_PER_BLK * 8 + T2 * 4 + ROWS_PER_BLK * 4)  // 126624

// ============================================================
// launch
// ============================================================
extern "C" void kernel_launch(void* const* d_in, const int* in_sizes, int n_in,
                              void* d_out, int out_size)
{
    const float* queries = (const float*)d_in[0];
    const float* keys    = (const float*)d_in[1];
    const float* prior   = (const float*)d_in[2];
    const float* kw1 = (const float*)d_in[3];
    const float* kb1 = (const float*)d_in[4];
    const float* kw2 = (const float*)d_in[5];
    const float* kb2 = (const float*)d_in[6];
    const float* qw1 = (const float*)d_in[7];
    const float* qb1 = (const float*)d_in[8];
    const float* qw2 = (const float*)d_in[9];
    const float* qb2 = (const float*)d_in[10];
    const float* qw3 = (const float*)d_in[11];
    const float* qb3 = (const float*)d_in[12];
    float* out = (float*)d_out;

    float *p_k1, *p_k, *p_q1, *p_q;
    cudaGetSymbolAddress((void**)&p_k1, g_k1);
    cudaGetSymbolAddress((void**)&p_k,  g_k);
    cudaGetSymbolAddress((void**)&p_q1, g_q1);
    cudaGetSymbolAddress((void**)&p_q,  g_q);

    const int SM_B = 2 * 16 * 68 * 4 + 2 * 80 * 17 * 8 + 80 * HROW * 4 + 6400 * 4; // 77824

    cudaFuncSetAttribute(convA, cudaFuncAttributeMaxDynamicSharedMemorySize, SM_A);
    cudaFuncSetAttribute(convB, cudaFuncAttributeMaxDynamicSharedMemorySize, SM_B);
    cudaFuncSetAttribute(attn_kernel, cudaFuncAttributeMaxDynamicSharedMemorySize, SM_ATT);

    prep_w<<<(KW1P_N + QW1P_N + 255) / 256, 256>>>(kw1, qw1);

    convA<<<KEY_A_BLKS + QRY_A_BLKS, 64, SM_A>>>(
        keys, kb1, p_k1, queries, qb1, p_q1);
    convB<<<KEY_B_BLKS + QRY_B_BLKS, 128, SM_B>>>(
        p_k1, kw2, kb2, p_k, p_q1, qw2, qb2, qw3, qb3, p_q);
    attn_kernel<<<dim3((T1 + ROWS_PER_BLK - 1) / ROWS_PER_BLK, B), 384, SM_ATT>>>(
        p_q, p_k, prior, out);
}

// round 11
// speedup vs baseline: 1.3995x; 1.0092x over previous
#include <cuda_runtime.h>
#include <math.h>

// ---------------- problem constants ----------------
#define B    16
#define T1   800
#define T2   200
#define CATT 80

typedef unsigned long long u64;

__device__ __forceinline__ u64 pk2(float lo, float hi) {
    u64 r; asm("mov.b64 %0,{%1,%2};" : "=l"(r) : "f"(lo), "f"(hi)); return r;
}
__device__ __forceinline__ void upk2(u64 v, float& lo, float& hi) {
    asm("mov.b64 {%0,%1},%2;" : "=f"(lo), "=f"(hi) : "l"(v));
}
__device__ __forceinline__ void ffma2(u64& d, u64 a, u64 b) {
    asm("fma.rn.f32x2 %0,%1,%2,%0;" : "+l"(d) : "l"(a), "l"(b));
}
__device__ __forceinline__ void cpa16(unsigned dst, const void* src) {
    asm volatile("cp.async.cg.shared.global [%0], [%1], 16;\n"
                 :: "r"(dst), "l"(src) : "memory");
}
#define CPA_COMMIT() asm volatile("cp.async.commit_group;\n" ::: "memory")
#define CPA_WAIT0()  asm volatile("cp.async.wait_group 0;\n" ::: "memory")

// ---------------- scratch ----------------
__device__ float g_k1[B * 512 * T2];   // key conv1 out
__device__ float g_k [B * CATT * T2];  // key encoder out
__device__ float g_q1[B * 160 * T1];   // query conv1 out
__device__ float g_q [B * CATT * T1];  // query encoder out

// pair-packed weights: [chunk c][co-pair][ck 0..7][tap 0..2] u64 = (w[2p], w[2p+1])
#define KW1P_N (32 * 256 * 24)   // 196608
#define QW1P_N (10 * 80 * 24)    // 19200
__device__ alignas(16) u64 g_kw1p[KW1P_N];
__device__ alignas(16) u64 g_qw1p[QW1P_N];

// ============================================================
// one-time weight pair-packing
// ============================================================
__global__ void prep_w(const float* __restrict__ kw1, const float* __restrict__ qw1)
{
    int idx = blockIdx.x * 256 + threadIdx.x;
    if (idx < KW1P_N) {
        int k  = idx % 3;
        int ck = (idx / 3) & 7;
        int p  = (idx / 24) & 255;
        int c  = idx / (24 * 256);
        int cin = c * 8 + ck;
        g_kw1p[idx] = pk2(kw1[(size_t)(2 * p) * 768 + cin * 3 + k],
                          kw1[(size_t)(2 * p + 1) * 768 + cin * 3 + k]);
    } else if (idx < KW1P_N + QW1P_N) {
        int j  = idx - KW1P_N;
        int k  = j % 3;
        int ck = (j / 3) & 7;
        int p  = (j / 24) % 80;
        int c  = j / (24 * 80);
        int cin = c * 8 + ck;
        g_qw1p[j] = pk2(qw1[(size_t)(2 * p) * 240 + cin * 3 + k],
                        qw1[(size_t)(2 * p + 1) * 240 + cin * 3 + k]);
    }
}

// ============================================================
// k=3 conv body, pad=1. 64 threads, micro 8co(4 pairs) x 8t(2 groups of 4).
// ============================================================
template<int TCO, int TT, int CIN, int RELU, int NPG>
__device__ __forceinline__ void conv3_pair(
    const float* __restrict__ xb,
    const u64*  __restrict__ wp,
    const float* __restrict__ bias,
    float* __restrict__ yb,
    int T, int co0, int t0, int tid, char* sm)
{
    constexpr int CK    = 8;
    constexpr int NC    = CIN / CK;
    constexpr int TTHR  = TT / 8;
    constexpr int COTHR = TCO / 8;
    static_assert(COTHR * TTHR == 64, "layout");
    constexpr int XCOLS = TT + 2;
    constexpr int XTOT  = CK * XCOLS;
    constexpr int XLD   = (XTOT + 63) / 64;
    constexpr int NP    = TCO / 2;
    constexpr int WOPS  = NP * 12;
    constexpr int WLD   = WOPS / 64;
    static_assert(WOPS % 64 == 0, "wops");
    constexpr int WPAD  = 26;
    constexpr int H     = TT / 2;

    u64* Xd = (u64*)sm;
    u64* Ws = Xd + 2 * CK * XCOLS;

    const int ci = tid / TTHR;
    const int tj = tid % TTHR;

    u64 acc[4][8];
    #pragma unroll
    for (int i = 0; i < 4; i++)
        #pragma unroll
        for (int j = 0; j < 8; j++) acc[i][j] = 0ull;

    float xr[XLD];

    auto ldgX = [&](int c) {
        #pragma unroll
        for (int i = 0; i < XLD; i++) {
            int e = tid + i * 64;
            float v = 0.f;
            if (e < XTOT) {
                int r = e / XCOLS, col = e % XCOLS;
                int t = t0 + col - 1;
                if (t >= 0 && t < T) v = xb[(size_t)(c * CK + r) * T + t];
            }
            xr[i] = v;
        }
    };
    auto stsX = [&](int buf) {
        u64* Xb = Xd + buf * CK * XCOLS;
        #pragma unroll
        for (int i = 0; i < XLD; i++) {
            int e = tid + i * 64;
            if (e < XTOT) Xb[e] = pk2(xr[i], xr[i]);
        }
    };
    auto cpaW = [&](int c, int buf) {
        const char* slab = (const char*)(wp + ((size_t)c * NPG + (co0 >> 1)) * 24);
        unsigned wbs = (unsigned)__cvta_generic_to_shared(Ws + buf * NP * WPAD);
        #pragma unroll
        for (int i = 0; i < WLD; i++) {
            int e = tid + i * 64;
            int p = e / 12, o = e % 12;
            cpa16(wbs + p * (WPAD * 8) + o * 16, slab + p * 192 + o * 16);
        }
        CPA_COMMIT();
    };

    cpaW(0, 0);
    ldgX(0);
    stsX(0);
    CPA_WAIT0();
    __syncthreads();

    for (int c = 0; c < NC; c++) {
        if (c + 1 < NC) {
            cpaW(c + 1, (c + 1) & 1);
            ldgX(c + 1);
        }
        {
            const u64* X = Xd + (c & 1) * CK * XCOLS;
            const u64* W = Ws + (c & 1) * NP * WPAD;
            #pragma unroll
            for (int ck = 0; ck < CK; ck++) {
                const u64* xrow = X + ck * XCOLS;
                ulonglong2 a0 = *(const ulonglong2*)(xrow + tj * 4);
                ulonglong2 a1 = *(const ulonglong2*)(xrow + tj * 4 + 2);
                ulonglong2 a2 = *(const ulonglong2*)(xrow + tj * 4 + 4);
                ulonglong2 b0 = *(const ulonglong2*)(xrow + tj * 4 + H);
                ulonglong2 b1 = *(const ulonglong2*)(xrow + tj * 4 + H + 2);
                ulonglong2 b2 = *(const ulonglong2*)(xrow + tj * 4 + H + 4);
                u64 d[6] = {a0.x, a0.y, a1.x, a1.y, a2.x, a2.y};
                u64 e2[6] = {b0.x, b0.y, b1.x, b1.y, b2.x, b2.y};
                #pragma unroll
                for (int i = 0; i < 4; i++) {
                    const u64* wr = W + (size_t)(ci * 4 + i) * WPAD + ck * 3;
                    u64 w0 = wr[0], w1 = wr[1], w2 = wr[2];
                    #pragma unroll
                    for (int j = 0; j < 4; j++) {
                        ffma2(acc[i][j], d[j],      w0);
                        ffma2(acc[i][j], d[j + 1],  w1);
                        ffma2(acc[i][j], d[j + 2],  w2);
                        ffma2(acc[i][4 + j], e2[j],     w0);
                        ffma2(acc[i][4 + j], e2[j + 1], w1);
                        ffma2(acc[i][4 + j], e2[j + 2], w2);
                    }
                }
            }
        }
        if (c + 1 < NC) {
            stsX((c + 1) & 1);
            CPA_WAIT0();
            __syncthreads();
        }
    }

    #pragma unroll
    for (int i = 0; i < 4; i++) {
        int coA = co0 + (ci * 4 + i) * 2;
        int coB = coA + 1;
        float bA = bias[coA], bB = bias[coB];
        #pragma unroll
        for (int g = 0; g < 2; g++) {
            int t = t0 + tj * 4 + g * H;
            if (t < T) {
                float a0, c0, a1, c1, a2, c2, a3, c3;
                upk2(acc[i][g * 4 + 0], a0, c0);
                upk2(acc[i][g * 4 + 1], a1, c1);
                upk2(acc[i][g * 4 + 2], a2, c2);
                upk2(acc[i][g * 4 + 3], a3, c3);
                float4 fA = make_float4(a0 + bA, a1 + bA, a2 + bA, a3 + bA);
                float4 fB = make_float4(c0 + bB, c1 + bB, c2 + bB, c3 + bB);
                if (RELU) {
                    fA.x = fmaxf(fA.x, 0.f); fA.y = fmaxf(fA.y, 0.f);
                    fA.z = fmaxf(fA.z, 0.f); fA.w = fmaxf(fA.w, 0.f);
                    fB.x = fmaxf(fB.x, 0.f); fB.y = fmaxf(fB.y, 0.f);
                    fB.z = fmaxf(fB.z, 0.f); fB.w = fmaxf(fB.w, 0.f);
                }
                *(float4*)(yb + (size_t)coA * T + t) = fA;
                *(float4*)(yb + (size_t)coB * T + t) = fB;
            }
        }
    }
}

// ---- kernel A ----
#define KEY_A_BLKS (4 * 7 * B)
#define QRY_A_BLKS (5 * 7 * B)
__global__ __launch_bounds__(64, 6) void convA(
    const float* __restrict__ keys, const float* __restrict__ kb1,
    float* __restrict__ k1out,
    const float* __restrict__ qsrc, const float* __restrict__ qb1,
    float* __restrict__ q1out)
{
    extern __shared__ char sm[];
    const int bid = blockIdx.x, tid = threadIdx.x;
    if (bid < KEY_A_BLKS) {
        int b = bid / 28, r = bid % 28;
        int co0 = (r / 7) * 128, t0 = (r % 7) * 32;
        conv3_pair<128, 32, 256, 1, 256>(keys + (size_t)b * 256 * T2, g_kw1p, kb1,
                                         k1out + (size_t)b * 512 * T2, T2, co0, t0, tid, sm);
    } else {
        int qb = bid - KEY_A_BLKS;
        int b = qb / 35, r = qb % 35;
        int co0 = (r / 7) * 32, t0 = (r % 7) * 128;
        conv3_pair<32, 128, 80, 1, 80>(qsrc + (size_t)b * 80 * T1, g_qw1p, qb1,
                                       q1out + (size_t)b * 160 * T1, T1, co0, t0, tid, sm);
    }
}
#define SM_A 30976

// ============================================================
// k=1 accumulate body
// ============================================================
template<int CIN>
__device__ __forceinline__ void k1_accum(
    const float* __restrict__ xb, int T, int t0,
    const float* __restrict__ w,
    float* Xs, float2* Ws, u64 (&acc)[5][4], int tid)
{
    constexpr int CK = 16, XROW = 68, WROW = 17;
    constexpr int NC = CIN / CK;
    constexpr int WLD = 80 * CK / 128;
    constexpr int XLD = CK * 64 / 128;
    const int ci = tid >> 3, tj = tid & 7;

    float wr_[WLD], xr_[XLD];
    #pragma unroll
    for (int i = 0; i < WLD; i++) {
        int e = tid + i * 128; int r = e / CK, cc = e % CK;
        wr_[i] = w[(size_t)r * CIN + cc];
    }
    #pragma unroll
    for (int i = 0; i < XLD; i++) {
        int e = tid + i * 128; int r = e / 64, cc = e % 64;
        int t = t0 + cc;
        xr_[i] = (t < T) ? xb[(size_t)r * T + t] : 0.f;
    }
    #pragma unroll
    for (int i = 0; i < WLD; i++) {
        int e = tid + i * 128; int r = e / CK, cc = e % CK;
        Ws[r * WROW + cc] = make_float2(wr_[i], wr_[i]);
    }
    #pragma unroll
    for (int i = 0; i < XLD; i++) {
        int e = tid + i * 128; int r = e / 64, cc = e % 64;
        Xs[r * XROW + cc] = xr_[i];
    }
    __syncthreads();

    for (int c = 0; c < NC; c++) {
        if (c + 1 < NC) {
            const int c0 = (c + 1) * CK;
            #pragma unroll
            for (int i = 0; i < WLD; i++) {
                int e = tid + i * 128; int r = e / CK, cc = e % CK;
                wr_[i] = w[(size_t)r * CIN + c0 + cc];
            }
            #pragma unroll
            for (int i = 0; i < XLD; i++) {
                int e = tid + i * 128; int r = e / 64, cc = e % 64;
                int t = t0 + cc;
                xr_[i] = (t < T) ? xb[(size_t)(c0 + r) * T + t] : 0.f;
            }
        }
        const float*  X = Xs + (c & 1) * CK * XROW;
        const float2* W = Ws + (c & 1) * 80 * WROW;
        #pragma unroll
        for (int ck = 0; ck < CK; ck++) {
            const ulonglong2* xp = (const ulonglong2*)(X + ck * XROW + tj * 8);
            ulonglong2 A = xp[0], Bv = xp[1];
            #pragma unroll
            for (int i = 0; i < 5; i++) {
                u64 wv = *(const u64*)(W + (size_t)(ci * 5 + i) * WROW + ck);
                ffma2(acc[i][0], A.x,  wv); ffma2(acc[i][1], A.y,  wv);
                ffma2(acc[i][2], Bv.x, wv); ffma2(acc[i][3], Bv.y, wv);
            }
        }
        if (c + 1 < NC) {
            __syncthreads();
            float*  Xd = Xs + ((c + 1) & 1) * CK * XROW;
            float2* Wd = Ws + ((c + 1) & 1) * 80 * WROW;
            #pragma unroll
            for (int i = 0; i < WLD; i++) {
                int e = tid + i * 128; int r = e / CK, cc = e % CK;
                Wd[r * WROW + cc] = make_float2(wr_[i], wr_[i]);
            }
            #pragma unroll
            for (int i = 0; i < XLD; i++) {
                int e = tid + i * 128; int r = e / 64, cc = e % 64;
                Xd[r * XROW + cc] = xr_[i];
            }
            __syncthreads();
        }
    }
}

// ---- kernel B ----
#define KEY_B_BLKS (4 * B)
#define QRY_B_BLKS (13 * B)
#define HROW 68
__global__ __launch_bounds__(128, 3) void convB(
    const float* __restrict__ k1in, const float* __restrict__ kw2,
    const float* __restrict__ kb2, float* __restrict__ kout,
    const float* __restrict__ q1in,
    const float* __restrict__ qw2, const float* __restrict__ qb2,
    const float* __restrict__ qw3, const float* __restrict__ qb3,
    float* __restrict__ qout)
{
    extern __shared__ char sm[];
    float*  Xs  = (float*)sm;
    float2* Ws  = (float2*)(sm + 2 * 16 * 68 * 4);
    float*  Hs  = (float*)((char*)Ws + 2 * 80 * 17 * 8);
    float*  W3s = Hs + 80 * HROW;

    const int bid = blockIdx.x, tid = threadIdx.x;
    const int ci = tid >> 3, tj = tid & 7;

    u64 acc[5][4];
    #pragma unroll
    for (int i = 0; i < 5; i++)
        #pragma unroll
        for (int p = 0; p < 4; p++) acc[i][p] = 0ull;

    if (bid < KEY_B_BLKS) {
        int b = bid / 4, t0 = (bid % 4) * 64;
        k1_accum<512>(k1in + (size_t)b * 512 * T2, T2, t0, kw2, Xs, Ws, acc, tid);
        float* yb = kout + (size_t)b * 80 * T2;
        #pragma unroll
        for (int i = 0; i < 5; i++) {
            int co = ci * 5 + i;
            float bb = kb2[co];
            float v[8];
            #pragma unroll
            for (int p = 0; p < 4; p++) upk2(acc[i][p], v[2 * p], v[2 * p + 1]);
            #pragma unroll
            for (int j = 0; j < 8; j++) {
                int t = t0 + tj * 8 + j;
                if (t < T2) yb[(size_t)co * T2 + t] = v[j] + bb;
            }
        }
    } else {
        int qb = bid - KEY_B_BLKS;
        int b = qb / 13, t0 = (qb % 13) * 64;
        for (int e = tid; e < 6400; e += 128) W3s[e] = qw3[e];
        k1_accum<160>(q1in + (size_t)b * 160 * T1, T1, t0, qw2, Xs, Ws, acc, tid);
        #pragma unroll
        for (int i = 0; i < 5; i++) {
            int co = ci * 5 + i;
            float bb = qb2[co];
            float v[8];
            #pragma unroll
            for (int p = 0; p < 4; p++) upk2(acc[i][p], v[2 * p], v[2 * p + 1]);
            float4 h0, h1;
            h0.x = fmaxf(v[0] + bb, 0.f); h0.y = fmaxf(v[1] + bb, 0.f);
            h0.z = fmaxf(v[2] + bb, 0.f); h0.w = fmaxf(v[3] + bb, 0.f);
            h1.x = fmaxf(v[4] + bb, 0.f); h1.y = fmaxf(v[5] + bb, 0.f);
            h1.z = fmaxf(v[6] + bb, 0.f); h1.w = fmaxf(v[7] + bb, 0.f);
            *(float4*)(Hs + (size_t)co * HROW + tj * 8) = h0;
            *(float4*)(Hs + (size_t)co * HROW + tj * 8 + 4) = h1;
        }
        __syncthreads();

        u64 acc2[5][4];
        #pragma unroll
        for (int i = 0; i < 5; i++)
            #pragma unroll
            for (int p = 0; p < 4; p++) acc2[i][p] = 0ull;

        #pragma unroll 4
        for (int ck = 0; ck < 80; ck++) {
            const ulonglong2* xp = (const ulonglong2*)(Hs + (size_t)ck * HROW + tj * 8);
            ulonglong2 A = xp[0], Bv = xp[1];
            #pragma unroll
            for (int i = 0; i < 5; i++) {
                float wv = W3s[(size_t)(ci * 5 + i) * 80 + ck];
                u64 wpk = pk2(wv, wv);
                ffma2(acc2[i][0], A.x,  wpk); ffma2(acc2[i][1], A.y,  wpk);
                ffma2(acc2[i][2], Bv.x, wpk); ffma2(acc2[i][3], Bv.y, wpk);
            }
        }

        float* yb = qout + (size_t)b * 80 * T1;
        #pragma unroll
        for (int i = 0; i < 5; i++) {
            int co = ci * 5 + i;
            float bb = qb3[co];
            float v[8];
            #pragma unroll
            for (int p = 0; p < 4; p++) upk2(acc2[i][p], v[2 * p], v[2 * p + 1]);
            #pragma unroll
            for (int j = 0; j < 8; j++) {
                int t = t0 + tj * 8 + j;
                if (t < T1) yb[(size_t)co * T1 + t] = v[j] + bb;
            }
        }
    }
}

// ============================================================
// Attention v4: 48 rows/block, 384 threads, 2 blocks/SM.
// t2-pair FFMA2 GEMM; softmax without max-shift (logits in (-1,0]).
// ============================================================
#define NPAIR 100
#define ROWS_PER_BLK 48
__global__ __launch_bounds__(384, 2) void attn_kernel(
    const float* __restrict__ q, const float* __restrict__ k,
    const float* __restrict__ prior, float* __restrict__ out)
{
    extern __shared__ char smc[];
    float* ks  = (float*)smc;                          // 80*200
    u64*   qd  = (u64*)(smc + 80 * T2 * 4);            // 80*48
    float* k2s = (float*)(qd + 80 * ROWS_PER_BLK);     // 200
    float* q2s = k2s + T2;                             // 48

    const int b   = blockIdx.y;
    const int t10 = blockIdx.x * ROWS_PER_BLK;
    const int tid = threadIdx.x;

    const float* kb = k + (size_t)b * CATT * T2;
    const float* qb = q + (size_t)b * CATT * T1;

    // load K (contiguous float4 copy)
    for (int i = tid; i < 80 * T2 / 4; i += 384)
        ((float4*)ks)[i] = ((const float4*)kb)[i];
    // load Q duplicated
    for (int i = tid; i < 80 * ROWS_PER_BLK; i += 384) {
        int c = i / ROWS_PER_BLK, r = i % ROWS_PER_BLK;
        int t = t10 + r;
        float v = (t < T1) ? qb[(size_t)c * T1 + t] : 0.f;
        qd[i] = pk2(v, v);
    }
    __syncthreads();

    // norms
    if (tid < T2) {
        float s = 0.f;
        #pragma unroll 8
        for (int c = 0; c < 80; c++) { float v = ks[c * T2 + tid]; s += v * v; }
        k2s[tid] = s;
    }
    if (tid >= 384 - ROWS_PER_BLK) {
        int r = tid - (384 - ROWS_PER_BLK);
        float s = 0.f;
        #pragma unroll 8
        for (int c = 0; c < 80; c++) {
            float lo, hi; upk2(qd[c * ROWS_PER_BLK + r], lo, hi); s += lo * lo;
        }
        q2s[r] = s;
    }
    __syncthreads();

    const int warp = tid >> 5, lane = tid & 31;
    const int o0 = lane, o1 = lane + 32, o2 = lane + 64;
    const int o3 = (lane < 4) ? lane + 96 : 0;   // clamped; masked later
    const bool v3 = (lane < 4);

    u64 dot[4][4];
    #pragma unroll
    for (int i = 0; i < 4; i++)
        #pragma unroll
        for (int j = 0; j < 4; j++) dot[i][j] = 0ull;

    const u64* kp = (const u64*)ks;
    #pragma unroll 2
    for (int c = 0; c < 80; c++) {
        u64 k0 = kp[c * NPAIR + o0];
        u64 k1 = kp[c * NPAIR + o1];
        u64 k2 = kp[c * NPAIR + o2];
        u64 k3 = kp[c * NPAIR + o3];
        const u64* qrow = qd + c * ROWS_PER_BLK + warp * 4;
        ulonglong2 qa = *(const ulonglong2*)qrow;
        ulonglong2 qbv = *(const ulonglong2*)(qrow + 2);
        u64 qv[4] = {qa.x, qa.y, qbv.x, qbv.y};
        #pragma unroll
        for (int i = 0; i < 4; i++) {
            ffma2(dot[i][0], qv[i], k0);
            ffma2(dot[i][1], qv[i], k1);
            ffma2(dot[i][2], qv[i], k2);
            ffma2(dot[i][3], qv[i], k3);
        }
    }

    const u64* k2p = (const u64*)k2s;
    u64 kn[4] = {k2p[o0], k2p[o1], k2p[o2], k2p[o3]};

    #pragma unroll
    for (int i = 0; i < 4; i++) {
        int r  = warp * 4 + i;
        int t1 = t10 + r;
        if (t1 >= T1) break;
        float q2 = q2s[r];

        // prefetch prior early (overlap LDG with reduction)
        const float2* pr = (const float2*)(prior + ((size_t)b * T1 + t1) * T2);
        float2 pv[4];
        pv[0] = pr[o0]; pv[1] = pr[o1]; pv[2] = pr[o2];
        if (v3) pv[3] = pr[o3];

        float xe[4], xo[4];
        #pragma unroll
        for (int j = 0; j < 4; j++) {
            float de, dofl, ke, ko;
            upk2(dot[i][j], de, dofl);
            upk2(kn[j], ke, ko);
            xe[j] = -0.0005f * (q2 + ke - 2.f * de);
            xo[j] = -0.0005f * (q2 + ko - 2.f * dofl);
        }
        // sum exp (no max shift: logits are O(-1..0), safe)
        float s = __expf(xe[0]) + __expf(xo[0])
                + __expf(xe[1]) + __expf(xo[1])
                + __expf(xe[2]) + __expf(xo[2]);
        if (v3) s += __expf(xe[3]) + __expf(xo[3]);
        #pragma unroll
        for (int off = 16; off; off >>= 1)
            s += __shfl_xor_sync(0xFFFFFFFFu, s, off);
        float lse = __logf(s);

        float2* ob = (float2*)(out + ((size_t)b * T1 + t1) * T2);
        #pragma unroll
        for (int j = 0; j < 4; j++) {
            if (j == 3 && !v3) break;
            int p = lane + 32 * j;
            float2 ov;
            ov.x = xe[j] - lse + __logf(pv[j].x + 1e-8f);
            ov.y = xo[j] - lse + __logf(pv[j].y + 1e-8f);
            ob[p] = ov;
        }
    }
}
#define SM_ATT (80 * T2 * 4 + 80 * ROWS_PER_BLK * 8 + T2 * 4 + ROWS_PER_BLK * 4)  // 95744

// ============================================================
// launch
// ============================================================
extern "C" void kernel_launch(void* const* d_in, const int* in_sizes, int n_in,
                              void* d_out, int out_size)
{
    const float* queries = (const float*)d_in[0];
    const float* keys    = (const float*)d_in[1];
    const float* prior   = (const float*)d_in[2];
    const float* kw1 = (const float*)d_in[3];
    const float* kb1 = (const float*)d_in[4];
    const float* kw2 = (const float*)d_in[5];
    const float* kb2 = (const float*)d_in[6];
    const float* qw1 = (const float*)d_in[7];
    const float* qb1 = (const float*)d_in[8];
    const float* qw2 = (const float*)d_in[9];
    const float* qb2 = (const float*)d_in[10];
    const float* qw3 = (const float*)d_in[11];
    const float* qb3 = (const float*)d_in[12];
    float* out = (float*)d_out;

    float *p_k1, *p_k, *p_q1, *p_q;
    cudaGetSymbolAddress((void**)&p_k1, g_k1);
    cudaGetSymbolAddress((void**)&p_k,  g_k);
    cudaGetSymbolAddress((void**)&p_q1, g_q1);
    cudaGetSymbolAddress((void**)&p_q,  g_q);

    const int SM_B = 2 * 16 * 68 * 4 + 2 * 80 * 17 * 8 + 80 * HROW * 4 + 6400 * 4; // 77824

    cudaFuncSetAttribute(convA, cudaFuncAttributeMaxDynamicSharedMemorySize, SM_A);
    cudaFuncSetAttribute(convB, cudaFuncAttributeMaxDynamicSharedMemorySize, SM_B);
    cudaFuncSetAttribute(attn_kernel, cudaFuncAttributeMaxDynamicSharedMemorySize, SM_ATT);

    prep_w<<<(KW1P_N + QW1P_N + 255) / 256, 256>>>(kw1, qw1);

    convA<<<KEY_A_BLKS + QRY_A_BLKS, 64, SM_A>>>(
        keys, kb1, p_k1, queries, qb1, p_q1);
    convB<<<KEY_B_BLKS + QRY_B_BLKS, 128, SM_B>>>(
        p_k1, kw2, kb2, p_k, p_q1, qw2, qb2, qw3, qb3, p_q);
    attn_kernel<<<dim3((T1 + ROWS_PER_BLK - 1) / ROWS_PER_BLK, B), 384, SM_ATT>>>(
        p_q, p_k, prior, out);
}